// round 1
// baseline (speedup 1.0000x reference)
#include <cuda_runtime.h>
#include <cuda_bf16.h>

// Problem constants
constexpr int NB  = 8;
constexpr int NS  = 1025;
constexpr int ND  = 768;
constexpr int NH  = 12;
constexpr int NHD = 64;
constexpr int NM  = NB * NS;      // 8200 rows for the QKV GEMMs

// Scratch: Q/K/V in [B, H, S, HD] layout (75.6 MB total, static device arrays)
__device__ float g_q[(size_t)NB * NH * NS * NHD];
__device__ float g_k[(size_t)NB * NH * NS * NHD];
__device__ float g_v[(size_t)NB * NH * NS * NHD];

// ---------------------------------------------------------------------------
// Kernel 1: fused QKV projection.
// C[m, n] = A[m, :] @ W[:, n] + bias[n], written to [B,H,S,HD] layout.
// blockIdx.z in {0,1,2} selects (Wq, Wk, Wv). Tile 64x64, BK=16, 256 threads,
// 4x4 register micro-tile per thread.
// ---------------------------------------------------------------------------
__global__ __launch_bounds__(256) void qkv_gemm_kernel(
    const float* __restrict__ A,
    const float* __restrict__ Wq, const float* __restrict__ bq,
    const float* __restrict__ Wk, const float* __restrict__ bk,
    const float* __restrict__ Wv, const float* __restrict__ bv)
{
    __shared__ float As[16][64];   // transposed: As[k][m]
    __shared__ float Bs[16][64];   // Bs[k][n]

    const int z = blockIdx.z;
    const float* W    = (z == 0) ? Wq : ((z == 1) ? Wk : Wv);
    const float* bias = (z == 0) ? bq : ((z == 1) ? bk : bv);
    float* outb       = (z == 0) ? g_q : ((z == 1) ? g_k : g_v);

    const int tid = threadIdx.x;
    const int tx = tid & 15;       // 0..15 -> n micro-col
    const int ty = tid >> 4;       // 0..15 -> m micro-row
    const int m0 = blockIdx.x * 64;
    const int n0 = blockIdx.y * 64;

    // A-tile load mapping: 64 rows x 16 cols = 256 float4
    const int arow = tid >> 2;           // 0..63
    const int ac4  = (tid & 3) * 4;      // 0,4,8,12
    // B-tile load mapping: 16 rows x 64 cols = 256 float4
    const int brow = tid >> 4;           // 0..15
    const int bc4  = (tid & 15) * 4;     // 0..60

    float acc[4][4] = {};

    for (int k0 = 0; k0 < ND; k0 += 16) {
        __syncthreads();
        // Load A tile (guard M tail), store transposed
        float4 av = make_float4(0.f, 0.f, 0.f, 0.f);
        if (m0 + arow < NM)
            av = *(const float4*)(A + (size_t)(m0 + arow) * ND + k0 + ac4);
        As[ac4 + 0][arow] = av.x;
        As[ac4 + 1][arow] = av.y;
        As[ac4 + 2][arow] = av.z;
        As[ac4 + 3][arow] = av.w;
        // Load W tile (N,K always in-bounds: 768 % 64 == 0)
        *(float4*)&Bs[brow][bc4] =
            *(const float4*)(W + (size_t)(k0 + brow) * ND + n0 + bc4);
        __syncthreads();

        #pragma unroll
        for (int kk = 0; kk < 16; kk++) {
            float4 a4 = *(float4*)&As[kk][ty * 4];
            float4 b4 = *(float4*)&Bs[kk][tx * 4];
            float ar[4] = {a4.x, a4.y, a4.z, a4.w};
            float br[4] = {b4.x, b4.y, b4.z, b4.w};
            #pragma unroll
            for (int i = 0; i < 4; i++)
                #pragma unroll
                for (int j = 0; j < 4; j++)
                    acc[i][j] += ar[i] * br[j];
        }
    }

    // Epilogue: n-tile covers exactly one head (n0 % 64 == 0, width 64)
    const int hh = n0 >> 6;
    #pragma unroll
    for (int i = 0; i < 4; i++) {
        const int m = m0 + ty * 4 + i;
        if (m >= NM) continue;
        const int bb = m / NS;
        const int ss = m - bb * NS;
        float4 o;
        o.x = acc[i][0] + bias[n0 + tx * 4 + 0];
        o.y = acc[i][1] + bias[n0 + tx * 4 + 1];
        o.z = acc[i][2] + bias[n0 + tx * 4 + 2];
        o.w = acc[i][3] + bias[n0 + tx * 4 + 3];
        *(float4*)(outb + (((size_t)bb * NH + hh) * NS + ss) * NHD + tx * 4) = o;
    }
}

// ---------------------------------------------------------------------------
// Kernel 2: flash attention. Block = (q-tile 64) x full K loop, online softmax.
// Grid (17 q-tiles, H, B), 256 threads, 4x4 register tiles for both GEMMs.
// ---------------------------------------------------------------------------
constexpr int BQ  = 64;
constexpr int BKT = 64;
constexpr int PAD = 68;   // row stride (floats): conflict-free-ish, 16B aligned
constexpr int SMEM_FLOATS = 4 * BQ * PAD + 3 * BQ;
constexpr int SMEM_BYTES  = SMEM_FLOATS * 4;   // 70400 B

__global__ __launch_bounds__(256) void attn_kernel(
    const float* __restrict__ bias, float* __restrict__ out)
{
    extern __shared__ float sm[];
    float* Qs    = sm;                    // [64][PAD]
    float* Ks    = Qs + BQ * PAD;         // [64][PAD]
    float* Vs    = Ks + BKT * PAD;        // [64][PAD]
    float* Ps    = Vs + BKT * PAD;        // [64][PAD] scores -> probs
    float* row_m = Ps + BQ * PAD;
    float* row_l = row_m + BQ;
    float* row_s = row_l + BQ;

    const int tid = threadIdx.x;
    const int tx = tid & 15;
    const int ty = tid >> 4;
    const int qt = blockIdx.x;
    const int h  = blockIdx.y;
    const int b  = blockIdx.z;
    const int q0 = qt * BQ;

    const float* Qg = g_q + ((size_t)(b * NH + h)) * NS * NHD;
    const float* Kg = g_k + ((size_t)(b * NH + h)) * NS * NHD;
    const float* Vg = g_v + ((size_t)(b * NH + h)) * NS * NHD;
    const float* Bg = bias + (size_t)h * NS * NS;

    // Load Q tile (zero-fill beyond S)
    #pragma unroll
    for (int u = 0; u < 4; u++) {
        int lin = u * 256 + tid;          // 0..1023
        int r   = lin >> 4;               // 0..63
        int c4  = (lin & 15) * 4;
        float4 v = make_float4(0.f, 0.f, 0.f, 0.f);
        if (q0 + r < NS) v = *(const float4*)(Qg + (size_t)(q0 + r) * NHD + c4);
        Qs[r * PAD + c4 + 0] = v.x;
        Qs[r * PAD + c4 + 1] = v.y;
        Qs[r * PAD + c4 + 2] = v.z;
        Qs[r * PAD + c4 + 3] = v.w;
    }
    if (tid < BQ) { row_m[tid] = -1e30f; row_l[tid] = 0.f; }

    float acc[4][4] = {};
    const int nkt = (NS + BKT - 1) / BKT;   // 17

    for (int kt = 0; kt < nkt; kt++) {
        const int k0 = kt * BKT;
        __syncthreads();   // covers Q load on first iter; Vs/Ps reuse after

        // Load K and V tiles (zero-fill beyond S)
        #pragma unroll
        for (int u = 0; u < 4; u++) {
            int lin = u * 256 + tid;
            int r   = lin >> 4;
            int c4  = (lin & 15) * 4;
            float4 kv = make_float4(0.f, 0.f, 0.f, 0.f);
            float4 vv = make_float4(0.f, 0.f, 0.f, 0.f);
            if (k0 + r < NS) {
                kv = *(const float4*)(Kg + (size_t)(k0 + r) * NHD + c4);
                vv = *(const float4*)(Vg + (size_t)(k0 + r) * NHD + c4);
            }
            Ks[r * PAD + c4 + 0] = kv.x;
            Ks[r * PAD + c4 + 1] = kv.y;
            Ks[r * PAD + c4 + 2] = kv.z;
            Ks[r * PAD + c4 + 3] = kv.w;
            Vs[r * PAD + c4 + 0] = vv.x;
            Vs[r * PAD + c4 + 1] = vv.y;
            Vs[r * PAD + c4 + 2] = vv.z;
            Vs[r * PAD + c4 + 3] = vv.w;
        }
        __syncthreads();

        // S = Q @ K^T (inner dim 64, float4 over d)
        float s[4][4] = {};
        #pragma unroll
        for (int d4 = 0; d4 < 16; d4++) {
            float4 qv[4], kv[4];
            #pragma unroll
            for (int i = 0; i < 4; i++)
                qv[i] = *(float4*)(Qs + (4 * ty + i) * PAD + d4 * 4);
            #pragma unroll
            for (int j = 0; j < 4; j++)
                kv[j] = *(float4*)(Ks + (4 * tx + j) * PAD + d4 * 4);
            #pragma unroll
            for (int i = 0; i < 4; i++)
                #pragma unroll
                for (int j = 0; j < 4; j++)
                    s[i][j] += qv[i].x * kv[j].x + qv[i].y * kv[j].y
                             + qv[i].z * kv[j].z + qv[i].w * kv[j].w;
        }

        // scale + bias + mask, write tile of scores to Ps
        #pragma unroll
        for (int i = 0; i < 4; i++) {
            const int q  = q0 + 4 * ty + i;
            const int qc = (q < NS) ? q : (NS - 1);
            const float* brow = Bg + (size_t)qc * NS + k0;
            #pragma unroll
            for (int j = 0; j < 4; j++) {
                const int k = k0 + 4 * tx + j;
                float val = (k < NS) ? (s[i][j] * 0.125f + brow[4 * tx + j])
                                     : -1e30f;
                Ps[(4 * ty + i) * PAD + 4 * tx + j] = val;
            }
        }
        __syncthreads();

        // Online softmax update: one thread per query row
        if (tid < BQ) {
            float mo = row_m[tid];
            float mn = mo;
            float* pr = Ps + tid * PAD;
            #pragma unroll 8
            for (int j = 0; j < BKT; j++) mn = fmaxf(mn, pr[j]);
            float sc = __expf(mo - mn);
            float l  = row_l[tid] * sc;
            #pragma unroll 8
            for (int j = 0; j < BKT; j++) {
                float p = __expf(pr[j] - mn);
                pr[j] = p;
                l += p;
            }
            row_m[tid] = mn;
            row_l[tid] = l;
            row_s[tid] = sc;
        }
        __syncthreads();

        // Rescale accumulators, then acc += P @ V
        float scl[4];
        #pragma unroll
        for (int i = 0; i < 4; i++) scl[i] = row_s[4 * ty + i];
        #pragma unroll
        for (int i = 0; i < 4; i++)
            #pragma unroll
            for (int j = 0; j < 4; j++)
                acc[i][j] *= scl[i];

        #pragma unroll 8
        for (int kk = 0; kk < BKT; kk++) {
            float4 vv = *(float4*)(Vs + kk * PAD + 4 * tx);
            float p[4];
            #pragma unroll
            for (int i = 0; i < 4; i++)
                p[i] = Ps[(4 * ty + i) * PAD + kk];
            #pragma unroll
            for (int i = 0; i < 4; i++) {
                acc[i][0] += p[i] * vv.x;
                acc[i][1] += p[i] * vv.y;
                acc[i][2] += p[i] * vv.z;
                acc[i][3] += p[i] * vv.w;
            }
        }
    }

    // Epilogue: out[b, q, h*64 + hd] = acc / l
    #pragma unroll
    for (int i = 0; i < 4; i++) {
        const int q = q0 + 4 * ty + i;
        if (q >= NS) continue;
        const float inv = 1.0f / row_l[4 * ty + i];
        float4 o;
        o.x = acc[i][0] * inv;
        o.y = acc[i][1] * inv;
        o.z = acc[i][2] * inv;
        o.w = acc[i][3] * inv;
        *(float4*)(out + ((size_t)b * NS + q) * ND + h * NHD + tx * 4) = o;
    }
}

// ---------------------------------------------------------------------------
extern "C" void kernel_launch(void* const* d_in, const int* in_sizes, int n_in,
                              void* d_out, int out_size)
{
    const float* hs = (const float*)d_in[0];   // hidden_states [B,S,D]
    const float* rb = (const float*)d_in[1];   // rel_bias [1,H,S,S]
    const float* Wq = (const float*)d_in[2];
    const float* bq = (const float*)d_in[3];
    const float* Wk = (const float*)d_in[4];
    const float* bk = (const float*)d_in[5];
    const float* Wv = (const float*)d_in[6];
    const float* bv = (const float*)d_in[7];
    float* out = (float*)d_out;

    // QKV projections
    dim3 g1((NM + 63) / 64, ND / 64, 3);
    qkv_gemm_kernel<<<g1, 256>>>(hs, Wq, bq, Wk, bk, Wv, bv);

    // Attention (dynamic smem 70400 B > 48K default -> raise the limit)
    cudaFuncSetAttribute(attn_kernel,
                         cudaFuncAttributeMaxDynamicSharedMemorySize,
                         SMEM_BYTES);
    dim3 g2((NS + BQ - 1) / BQ, NH, NB);
    attn_kernel<<<g2, 256, SMEM_BYTES>>>(rb, out);
}

// round 4
// speedup vs baseline: 1.3212x; 1.3212x over previous
#include <cuda_runtime.h>
#include <cuda_bf16.h>
#include <cstdint>

// Problem constants
constexpr int NB  = 8;
constexpr int NS  = 1025;
constexpr int ND  = 768;
constexpr int NH  = 12;
constexpr int NHD = 64;
constexpr int NM  = NB * NS;      // 8200

// Scratch
__device__ float g_q[(size_t)NB * NH * NS * NHD];
__device__ float g_k[(size_t)NB * NH * NS * NHD];
__device__ float g_v[(size_t)NB * NH * NS * NHD];
__device__ __nv_bfloat16 g_ahi[(size_t)NM * ND];
__device__ __nv_bfloat16 g_alo[(size_t)NM * ND];
__device__ __nv_bfloat16 g_wthi[(size_t)3 * ND * ND];   // transposed: [n][k]
__device__ __nv_bfloat16 g_wtlo[(size_t)3 * ND * ND];

// ---------------------------------------------------------------------------
// mma.sync helpers (plain PTX, valid on bare sm_103 target)
// ---------------------------------------------------------------------------
__device__ __forceinline__ uint32_t smem_to_u32(const void* p) {
    uint32_t a;
    asm("{ .reg .u64 t; cvta.to.shared.u64 t, %1; cvt.u32.u64 %0, t; }"
        : "=r"(a) : "l"(p));
    return a;
}

__device__ __forceinline__ void ldsm_x4(uint32_t& r0, uint32_t& r1,
                                        uint32_t& r2, uint32_t& r3,
                                        uint32_t addr) {
    asm volatile("ldmatrix.sync.aligned.m8n8.x4.shared.b16 {%0,%1,%2,%3}, [%4];"
                 : "=r"(r0), "=r"(r1), "=r"(r2), "=r"(r3) : "r"(addr));
}

__device__ __forceinline__ void mma_16816_bf16(
    float& c0, float& c1, float& c2, float& c3,
    uint32_t a0, uint32_t a1, uint32_t a2, uint32_t a3,
    uint32_t b0, uint32_t b1) {
    asm volatile(
        "mma.sync.aligned.m16n8k16.row.col.f32.bf16.bf16.f32 "
        "{%0,%1,%2,%3}, {%4,%5,%6,%7}, {%8,%9}, {%0,%1,%2,%3};"
        : "+f"(c0), "+f"(c1), "+f"(c2), "+f"(c3)
        : "r"(a0), "r"(a1), "r"(a2), "r"(a3), "r"(b0), "r"(b1));
}

// ---------------------------------------------------------------------------
// Kernel A: split hidden_states fp32 -> (hi, lo) bf16
// ---------------------------------------------------------------------------
__global__ __launch_bounds__(256) void aconv_kernel(const float* __restrict__ A)
{
    size_t i = ((size_t)blockIdx.x * 256 + threadIdx.x) * 4;
    if (i >= (size_t)NM * ND) return;
    float4 v = *(const float4*)(A + i);
    __nv_bfloat16 h0 = __float2bfloat16(v.x), h1 = __float2bfloat16(v.y);
    __nv_bfloat16 h2 = __float2bfloat16(v.z), h3 = __float2bfloat16(v.w);
    __nv_bfloat16 l0 = __float2bfloat16(v.x - __bfloat162float(h0));
    __nv_bfloat16 l1 = __float2bfloat16(v.y - __bfloat162float(h1));
    __nv_bfloat16 l2 = __float2bfloat16(v.z - __bfloat162float(h2));
    __nv_bfloat16 l3 = __float2bfloat16(v.w - __bfloat162float(h3));
    *(__nv_bfloat162*)(g_ahi + i)     = __halves2bfloat162(h0, h1);
    *(__nv_bfloat162*)(g_ahi + i + 2) = __halves2bfloat162(h2, h3);
    *(__nv_bfloat162*)(g_alo + i)     = __halves2bfloat162(l0, l1);
    *(__nv_bfloat162*)(g_alo + i + 2) = __halves2bfloat162(l2, l3);
}

// ---------------------------------------------------------------------------
// Kernel B: transpose + split W fp32 [K,N] -> Wt (hi,lo) bf16 [N,K]
// ---------------------------------------------------------------------------
__global__ __launch_bounds__(256) void wtrans_kernel(
    const float* __restrict__ Wq, const float* __restrict__ Wk,
    const float* __restrict__ Wv)
{
    __shared__ float t[32][33];
    const int z = blockIdx.z;
    const float* W = (z == 0) ? Wq : ((z == 1) ? Wk : Wv);
    __nv_bfloat16* hi = g_wthi + (size_t)z * ND * ND;
    __nv_bfloat16* lo = g_wtlo + (size_t)z * ND * ND;
    const int n0 = blockIdx.x * 32, k0 = blockIdx.y * 32;
    const int tx = threadIdx.x, ty = threadIdx.y;   // (32, 8)
    #pragma unroll
    for (int i = 0; i < 32; i += 8)
        t[ty + i][tx] = W[(size_t)(k0 + ty + i) * ND + n0 + tx];
    __syncthreads();
    #pragma unroll
    for (int i = 0; i < 32; i += 8) {
        float v = t[tx][ty + i];   // = W[k0+tx][n0+ty+i]
        __nv_bfloat16 h = __float2bfloat16(v);
        hi[(size_t)(n0 + ty + i) * ND + k0 + tx] = h;
        lo[(size_t)(n0 + ty + i) * ND + k0 + tx] =
            __float2bfloat16(v - __bfloat162float(h));
    }
}

// ---------------------------------------------------------------------------
// Kernel C: QKV projection with mma.sync (HMMA) bf16 3-way split, fp32 accum.
// CTA tile: 128(m) x 64(n), BK=64, 8 warps as 4(m) x 2(n), 32x32 per warp.
// Grid (65, 12, 3).
// ---------------------------------------------------------------------------
constexpr int LDA = 72;                 // smem row stride in bf16 elems (144 B)
constexpr int SMQ_AHI = 0;              // 128 x LDA bf16 = 18432 B
constexpr int SMQ_ALO = SMQ_AHI + 128 * LDA * 2;
constexpr int SMQ_BHI = SMQ_ALO + 128 * LDA * 2;   // 64 x LDA = 9216 B
constexpr int SMQ_BLO = SMQ_BHI + 64 * LDA * 2;
constexpr int SMQ_TOT = SMQ_BLO + 64 * LDA * 2;    // 55296 B

__global__ __launch_bounds__(256) void qkv_hmma_kernel(
    const float* __restrict__ bq, const float* __restrict__ bk,
    const float* __restrict__ bv)
{
    extern __shared__ char smem[];
    const uint32_t smem_base = smem_to_u32(smem);
    const int tid = threadIdx.x, wid = tid >> 5, lane = tid & 31;
    const int z  = blockIdx.z;
    const int m0 = blockIdx.x * 128;
    const int h  = blockIdx.y;
    const int n0 = h * 64;
    const float* bias = (z == 0) ? bq : ((z == 1) ? bk : bv);
    float* outb       = (z == 0) ? g_q : ((z == 1) ? g_k : g_v);
    const __nv_bfloat16* Bh = g_wthi + (size_t)z * ND * ND;
    const __nv_bfloat16* Bl = g_wtlo + (size_t)z * ND * ND;

    const int wm = wid >> 1;            // 0..3 -> 32-row slab
    const int wn = wid & 1;             // 0..1 -> 32-col slab

    // ldmatrix lane addressing: mi = lane>>3 selects the 8x8 submatrix,
    // r = lane&7 the row within it.
    const int mi = lane >> 3, lr = lane & 7;
    // element offset within a tile placed at (row0, col0):
    //   (row0 + (mi&1)*8 + r) * LDA + col0 + (mi>>1)*8
    const int ld_row = (mi & 1) * 8 + lr;
    const int ld_col = (mi >> 1) * 8;

    float acc[2][4][4] = {};

    for (int ch = 0; ch < 12; ch++) {
        const int k0 = ch * 64;
        __syncthreads();
        // ---- load A tiles (128 x 64 bf16, hi+lo), guard m tail ----
        #pragma unroll
        for (int it = 0; it < 4; it++) {
            int lin = it * 256 + tid;
            int row = lin >> 3, c8 = (lin & 7) * 8;
            int m = m0 + row;
            uint4 vh = make_uint4(0, 0, 0, 0), vl = make_uint4(0, 0, 0, 0);
            if (m < NM) {
                vh = *(const uint4*)(g_ahi + (size_t)m * ND + k0 + c8);
                vl = *(const uint4*)(g_alo + (size_t)m * ND + k0 + c8);
            }
            *(uint4*)(smem + SMQ_AHI + (row * LDA + c8) * 2) = vh;
            *(uint4*)(smem + SMQ_ALO + (row * LDA + c8) * 2) = vl;
        }
        // ---- load B tiles (64 x 64 bf16, hi+lo); always in-bounds ----
        #pragma unroll
        for (int it = 0; it < 2; it++) {
            int lin = it * 256 + tid;
            int row = lin >> 3, c8 = (lin & 7) * 8;
            *(uint4*)(smem + SMQ_BHI + (row * LDA + c8) * 2) =
                *(const uint4*)(Bh + (size_t)(n0 + row) * ND + k0 + c8);
            *(uint4*)(smem + SMQ_BLO + (row * LDA + c8) * 2) =
                *(const uint4*)(Bl + (size_t)(n0 + row) * ND + k0 + c8);
        }
        __syncthreads();

        #pragma unroll
        for (int k16 = 0; k16 < 4; k16++) {
            const int kc = k16 * 16 + ld_col;
            // A frags: hi and lo, 2 m-frags each (16x16 tiles)
            uint32_t ah[2][4], al[2][4];
            #pragma unroll
            for (int mf = 0; mf < 2; mf++) {
                uint32_t off =
                    (uint32_t)(((wm * 32 + mf * 16 + ld_row) * LDA + kc) * 2);
                ldsm_x4(ah[mf][0], ah[mf][1], ah[mf][2], ah[mf][3],
                        smem_base + SMQ_AHI + off);
                ldsm_x4(al[mf][0], al[mf][1], al[mf][2], al[mf][3],
                        smem_base + SMQ_ALO + off);
            }
            // B frags: hi and lo, 4 n-frags each. One x4 over 16 n-rows
            // yields frags (nf, nf+1): reg pairs (m0,m2) and (m1,m3).
            uint32_t bh[4][2], bl[4][2];
            #pragma unroll
            for (int nf2 = 0; nf2 < 2; nf2++) {
                uint32_t off =
                    (uint32_t)(((wn * 32 + nf2 * 16 + ld_row) * LDA + kc) * 2);
                uint32_t t0, t1, t2, t3;
                ldsm_x4(t0, t1, t2, t3, smem_base + SMQ_BHI + off);
                bh[nf2 * 2 + 0][0] = t0; bh[nf2 * 2 + 0][1] = t2;
                bh[nf2 * 2 + 1][0] = t1; bh[nf2 * 2 + 1][1] = t3;
                ldsm_x4(t0, t1, t2, t3, smem_base + SMQ_BLO + off);
                bl[nf2 * 2 + 0][0] = t0; bl[nf2 * 2 + 0][1] = t2;
                bl[nf2 * 2 + 1][0] = t1; bl[nf2 * 2 + 1][1] = t3;
            }
            // 3 passes: Ahi*Bhi + Alo*Bhi + Ahi*Blo
            #pragma unroll
            for (int mf = 0; mf < 2; mf++)
                #pragma unroll
                for (int nf = 0; nf < 4; nf++) {
                    float* c = acc[mf][nf];
                    mma_16816_bf16(c[0], c[1], c[2], c[3],
                                   ah[mf][0], ah[mf][1], ah[mf][2], ah[mf][3],
                                   bh[nf][0], bh[nf][1]);
                    mma_16816_bf16(c[0], c[1], c[2], c[3],
                                   al[mf][0], al[mf][1], al[mf][2], al[mf][3],
                                   bh[nf][0], bh[nf][1]);
                    mma_16816_bf16(c[0], c[1], c[2], c[3],
                                   ah[mf][0], ah[mf][1], ah[mf][2], ah[mf][3],
                                   bl[nf][0], bl[nf][1]);
                }
        }
    }

    // ---- epilogue: d-frag layout m16n8: row = lane>>2 (+8), col = (lane&3)*2
    const int er = lane >> 2, ec = (lane & 3) * 2;
    #pragma unroll
    for (int mf = 0; mf < 2; mf++) {
        #pragma unroll
        for (int half = 0; half < 2; half++) {
            const int m = m0 + wm * 32 + mf * 16 + er + half * 8;
            if (m >= NM) continue;
            const int bb = m / NS, ss = m - bb * NS;
            float* op = outb + (((size_t)bb * NH + h) * NS + ss) * NHD;
            #pragma unroll
            for (int nf = 0; nf < 4; nf++) {
                const int c = wn * 32 + nf * 8 + ec;
                float2 o;
                o.x = acc[mf][nf][half * 2 + 0] + bias[n0 + c + 0];
                o.y = acc[mf][nf][half * 2 + 1] + bias[n0 + c + 1];
                *(float2*)(op + c) = o;
            }
        }
    }
}

// ---------------------------------------------------------------------------
// Kernel D: flash attention (unchanged)
// ---------------------------------------------------------------------------
constexpr int BQ  = 64;
constexpr int BKT = 64;
constexpr int PAD = 68;
constexpr int SMEM_FLOATS = 4 * BQ * PAD + 3 * BQ;
constexpr int SMEM_BYTES  = SMEM_FLOATS * 4;

__global__ __launch_bounds__(256) void attn_kernel(
    const float* __restrict__ bias, float* __restrict__ out)
{
    extern __shared__ float sm[];
    float* Qs    = sm;
    float* Ks    = Qs + BQ * PAD;
    float* Vs    = Ks + BKT * PAD;
    float* Ps    = Vs + BKT * PAD;
    float* row_m = Ps + BQ * PAD;
    float* row_l = row_m + BQ;
    float* row_s = row_l + BQ;

    const int tid = threadIdx.x;
    const int tx = tid & 15;
    const int ty = tid >> 4;
    const int qt = blockIdx.x;
    const int h  = blockIdx.y;
    const int b  = blockIdx.z;
    const int q0 = qt * BQ;

    const float* Qg = g_q + ((size_t)(b * NH + h)) * NS * NHD;
    const float* Kg = g_k + ((size_t)(b * NH + h)) * NS * NHD;
    const float* Vg = g_v + ((size_t)(b * NH + h)) * NS * NHD;
    const float* Bg = bias + (size_t)h * NS * NS;

    #pragma unroll
    for (int u = 0; u < 4; u++) {
        int lin = u * 256 + tid;
        int r   = lin >> 4;
        int c4  = (lin & 15) * 4;
        float4 v = make_float4(0.f, 0.f, 0.f, 0.f);
        if (q0 + r < NS) v = *(const float4*)(Qg + (size_t)(q0 + r) * NHD + c4);
        Qs[r * PAD + c4 + 0] = v.x;
        Qs[r * PAD + c4 + 1] = v.y;
        Qs[r * PAD + c4 + 2] = v.z;
        Qs[r * PAD + c4 + 3] = v.w;
    }
    if (tid < BQ) { row_m[tid] = -1e30f; row_l[tid] = 0.f; }

    float acc[4][4] = {};
    const int nkt = (NS + BKT - 1) / BKT;

    for (int kt = 0; kt < nkt; kt++) {
        const int k0 = kt * BKT;
        __syncthreads();

        #pragma unroll
        for (int u = 0; u < 4; u++) {
            int lin = u * 256 + tid;
            int r   = lin >> 4;
            int c4  = (lin & 15) * 4;
            float4 kv = make_float4(0.f, 0.f, 0.f, 0.f);
            float4 vv = make_float4(0.f, 0.f, 0.f, 0.f);
            if (k0 + r < NS) {
                kv = *(const float4*)(Kg + (size_t)(k0 + r) * NHD + c4);
                vv = *(const float4*)(Vg + (size_t)(k0 + r) * NHD + c4);
            }
            Ks[r * PAD + c4 + 0] = kv.x;
            Ks[r * PAD + c4 + 1] = kv.y;
            Ks[r * PAD + c4 + 2] = kv.z;
            Ks[r * PAD + c4 + 3] = kv.w;
            Vs[r * PAD + c4 + 0] = vv.x;
            Vs[r * PAD + c4 + 1] = vv.y;
            Vs[r * PAD + c4 + 2] = vv.z;
            Vs[r * PAD + c4 + 3] = vv.w;
        }
        __syncthreads();

        float s[4][4] = {};
        #pragma unroll
        for (int d4 = 0; d4 < 16; d4++) {
            float4 qv[4], kv[4];
            #pragma unroll
            for (int i = 0; i < 4; i++)
                qv[i] = *(float4*)(Qs + (4 * ty + i) * PAD + d4 * 4);
            #pragma unroll
            for (int j = 0; j < 4; j++)
                kv[j] = *(float4*)(Ks + (4 * tx + j) * PAD + d4 * 4);
            #pragma unroll
            for (int i = 0; i < 4; i++)
                #pragma unroll
                for (int j = 0; j < 4; j++)
                    s[i][j] += qv[i].x * kv[j].x + qv[i].y * kv[j].y
                             + qv[i].z * kv[j].z + qv[i].w * kv[j].w;
        }

        #pragma unroll
        for (int i = 0; i < 4; i++) {
            const int q  = q0 + 4 * ty + i;
            const int qc = (q < NS) ? q : (NS - 1);
            const float* brow = Bg + (size_t)qc * NS + k0;
            #pragma unroll
            for (int j = 0; j < 4; j++) {
                const int k = k0 + 4 * tx + j;
                float val = (k < NS) ? (s[i][j] * 0.125f + brow[4 * tx + j])
                                     : -1e30f;
                Ps[(4 * ty + i) * PAD + 4 * tx + j] = val;
            }
        }
        __syncthreads();

        if (tid < BQ) {
            float mo = row_m[tid];
            float mn = mo;
            float* pr = Ps + tid * PAD;
            #pragma unroll 8
            for (int j = 0; j < BKT; j++) mn = fmaxf(mn, pr[j]);
            float sc = __expf(mo - mn);
            float l  = row_l[tid] * sc;
            #pragma unroll 8
            for (int j = 0; j < BKT; j++) {
                float p = __expf(pr[j] - mn);
                pr[j] = p;
                l += p;
            }
            row_m[tid] = mn;
            row_l[tid] = l;
            row_s[tid] = sc;
        }
        __syncthreads();

        float scl[4];
        #pragma unroll
        for (int i = 0; i < 4; i++) scl[i] = row_s[4 * ty + i];
        #pragma unroll
        for (int i = 0; i < 4; i++)
            #pragma unroll
            for (int j = 0; j < 4; j++)
                acc[i][j] *= scl[i];

        #pragma unroll 8
        for (int kk = 0; kk < BKT; kk++) {
            float4 vv = *(float4*)(Vs + kk * PAD + 4 * tx);
            float p[4];
            #pragma unroll
            for (int i = 0; i < 4; i++)
                p[i] = Ps[(4 * ty + i) * PAD + kk];
            #pragma unroll
            for (int i = 0; i < 4; i++) {
                acc[i][0] += p[i] * vv.x;
                acc[i][1] += p[i] * vv.y;
                acc[i][2] += p[i] * vv.z;
                acc[i][3] += p[i] * vv.w;
            }
        }
    }

    #pragma unroll
    for (int i = 0; i < 4; i++) {
        const int q = q0 + 4 * ty + i;
        if (q >= NS) continue;
        const float inv = 1.0f / row_l[4 * ty + i];
        float4 o;
        o.x = acc[i][0] * inv;
        o.y = acc[i][1] * inv;
        o.z = acc[i][2] * inv;
        o.w = acc[i][3] * inv;
        *(float4*)(out + ((size_t)b * NS + q) * ND + h * NHD + tx * 4) = o;
    }
}

// ---------------------------------------------------------------------------
extern "C" void kernel_launch(void* const* d_in, const int* in_sizes, int n_in,
                              void* d_out, int out_size)
{
    const float* hs = (const float*)d_in[0];
    const float* rb = (const float*)d_in[1];
    const float* Wq = (const float*)d_in[2];
    const float* bq = (const float*)d_in[3];
    const float* Wk = (const float*)d_in[4];
    const float* bk = (const float*)d_in[5];
    const float* Wv = (const float*)d_in[6];
    const float* bv = (const float*)d_in[7];
    float* out = (float*)d_out;

    // Split conversions
    aconv_kernel<<<(int)(((size_t)NM * ND / 4 + 255) / 256), 256>>>(hs);
    dim3 gw(ND / 32, ND / 32, 3);
    wtrans_kernel<<<gw, dim3(32, 8)>>>(Wq, Wk, Wv);

    // QKV projection on HMMA tensor cores
    cudaFuncSetAttribute(qkv_hmma_kernel,
                         cudaFuncAttributeMaxDynamicSharedMemorySize, SMQ_TOT);
    dim3 g1((NM + 127) / 128, NH, 3);
    qkv_hmma_kernel<<<g1, 256, SMQ_TOT>>>(bq, bk, bv);

    // Attention
    cudaFuncSetAttribute(attn_kernel,
                         cudaFuncAttributeMaxDynamicSharedMemorySize, SMEM_BYTES);
    dim3 g2((NS + BQ - 1) / BQ, NH, NB);
    attn_kernel<<<g2, 256, SMEM_BYTES>>>(rb, out);
}

// round 6
// speedup vs baseline: 3.8723x; 2.9310x over previous
#include <cuda_runtime.h>
#include <cuda_bf16.h>
#include <cuda_fp16.h>
#include <cstdint>

// Problem constants
constexpr int NB  = 8;
constexpr int NS  = 1025;
constexpr int ND  = 768;
constexpr int NH  = 12;
constexpr int NHD = 64;
constexpr int NM  = NB * NS;      // 8200

// Scratch
__device__ __half g_qh[(size_t)NB * NH * NS * NHD];   // q * 0.125, fp16
__device__ __half g_kh[(size_t)NB * NH * NS * NHD];
__device__ __half g_vh[(size_t)NB * NH * NS * NHD];
__device__ __nv_bfloat16 g_ahi[(size_t)NM * ND];
__device__ __nv_bfloat16 g_alo[(size_t)NM * ND];
__device__ __nv_bfloat16 g_wthi[(size_t)3 * ND * ND];   // transposed: [n][k]
__device__ __nv_bfloat16 g_wtlo[(size_t)3 * ND * ND];

// ---------------------------------------------------------------------------
// PTX helpers
// ---------------------------------------------------------------------------
__device__ __forceinline__ uint32_t smem_to_u32(const void* p) {
    uint32_t a;
    asm("{ .reg .u64 t; cvta.to.shared.u64 t, %1; cvt.u32.u64 %0, t; }"
        : "=r"(a) : "l"(p));
    return a;
}
__device__ __forceinline__ void ldsm_x4(uint32_t& r0, uint32_t& r1,
                                        uint32_t& r2, uint32_t& r3,
                                        uint32_t addr) {
    asm volatile("ldmatrix.sync.aligned.m8n8.x4.shared.b16 {%0,%1,%2,%3}, [%4];"
                 : "=r"(r0), "=r"(r1), "=r"(r2), "=r"(r3) : "r"(addr));
}
__device__ __forceinline__ void ldsm_x4_trans(uint32_t& r0, uint32_t& r1,
                                              uint32_t& r2, uint32_t& r3,
                                              uint32_t addr) {
    asm volatile("ldmatrix.sync.aligned.m8n8.x4.trans.shared.b16 {%0,%1,%2,%3}, [%4];"
                 : "=r"(r0), "=r"(r1), "=r"(r2), "=r"(r3) : "r"(addr));
}
__device__ __forceinline__ void mma_16816_bf16(
    float& c0, float& c1, float& c2, float& c3,
    uint32_t a0, uint32_t a1, uint32_t a2, uint32_t a3,
    uint32_t b0, uint32_t b1) {
    asm volatile(
        "mma.sync.aligned.m16n8k16.row.col.f32.bf16.bf16.f32 "
        "{%0,%1,%2,%3}, {%4,%5,%6,%7}, {%8,%9}, {%0,%1,%2,%3};"
        : "+f"(c0), "+f"(c1), "+f"(c2), "+f"(c3)
        : "r"(a0), "r"(a1), "r"(a2), "r"(a3), "r"(b0), "r"(b1));
}
__device__ __forceinline__ void mma_16816_f16(
    float& c0, float& c1, float& c2, float& c3,
    uint32_t a0, uint32_t a1, uint32_t a2, uint32_t a3,
    uint32_t b0, uint32_t b1) {
    asm volatile(
        "mma.sync.aligned.m16n8k16.row.col.f32.f16.f16.f32 "
        "{%0,%1,%2,%3}, {%4,%5,%6,%7}, {%8,%9}, {%0,%1,%2,%3};"
        : "+f"(c0), "+f"(c1), "+f"(c2), "+f"(c3)
        : "r"(a0), "r"(a1), "r"(a2), "r"(a3), "r"(b0), "r"(b1));
}
__device__ __forceinline__ uint32_t pack_h2(float lo, float hi) {
    uint32_t r;
    asm("cvt.rn.f16x2.f32 %0, %1, %2;" : "=r"(r) : "f"(hi), "f"(lo));
    return r;
}

// ---------------------------------------------------------------------------
// Kernel A: split hidden_states fp32 -> (hi, lo) bf16
// ---------------------------------------------------------------------------
__global__ __launch_bounds__(256) void aconv_kernel(const float* __restrict__ A)
{
    size_t i = ((size_t)blockIdx.x * 256 + threadIdx.x) * 4;
    if (i >= (size_t)NM * ND) return;
    float4 v = *(const float4*)(A + i);
    __nv_bfloat16 h0 = __float2bfloat16(v.x), h1 = __float2bfloat16(v.y);
    __nv_bfloat16 h2 = __float2bfloat16(v.z), h3 = __float2bfloat16(v.w);
    __nv_bfloat16 l0 = __float2bfloat16(v.x - __bfloat162float(h0));
    __nv_bfloat16 l1 = __float2bfloat16(v.y - __bfloat162float(h1));
    __nv_bfloat16 l2 = __float2bfloat16(v.z - __bfloat162float(h2));
    __nv_bfloat16 l3 = __float2bfloat16(v.w - __bfloat162float(h3));
    *(__nv_bfloat162*)(g_ahi + i)     = __halves2bfloat162(h0, h1);
    *(__nv_bfloat162*)(g_ahi + i + 2) = __halves2bfloat162(h2, h3);
    *(__nv_bfloat162*)(g_alo + i)     = __halves2bfloat162(l0, l1);
    *(__nv_bfloat162*)(g_alo + i + 2) = __halves2bfloat162(l2, l3);
}

// ---------------------------------------------------------------------------
// Kernel B: transpose + split W fp32 [K,N] -> Wt (hi,lo) bf16 [N,K]
// ---------------------------------------------------------------------------
__global__ __launch_bounds__(256) void wtrans_kernel(
    const float* __restrict__ Wq, const float* __restrict__ Wk,
    const float* __restrict__ Wv)
{
    __shared__ float t[32][33];
    const int z = blockIdx.z;
    const float* W = (z == 0) ? Wq : ((z == 1) ? Wk : Wv);
    __nv_bfloat16* hi = g_wthi + (size_t)z * ND * ND;
    __nv_bfloat16* lo = g_wtlo + (size_t)z * ND * ND;
    const int n0 = blockIdx.x * 32, k0 = blockIdx.y * 32;
    const int tx = threadIdx.x, ty = threadIdx.y;   // (32, 8)
    #pragma unroll
    for (int i = 0; i < 32; i += 8)
        t[ty + i][tx] = W[(size_t)(k0 + ty + i) * ND + n0 + tx];
    __syncthreads();
    #pragma unroll
    for (int i = 0; i < 32; i += 8) {
        float v = t[tx][ty + i];
        __nv_bfloat16 h = __float2bfloat16(v);
        hi[(size_t)(n0 + ty + i) * ND + k0 + tx] = h;
        lo[(size_t)(n0 + ty + i) * ND + k0 + tx] =
            __float2bfloat16(v - __bfloat162float(h));
    }
}

// ---------------------------------------------------------------------------
// Kernel C: QKV projection HMMA (bf16 3-way split, fp32 accum), fp16 output.
// CTA tile 128x64, BK=64, 8 warps 4x2. Grid (65, 12, 3). Q scaled by 0.125.
// ---------------------------------------------------------------------------
constexpr int LDA = 72;
constexpr int SMQ_AHI = 0;
constexpr int SMQ_ALO = SMQ_AHI + 128 * LDA * 2;
constexpr int SMQ_BHI = SMQ_ALO + 128 * LDA * 2;
constexpr int SMQ_BLO = SMQ_BHI + 64 * LDA * 2;
constexpr int SMQ_TOT = SMQ_BLO + 64 * LDA * 2;    // 55296 B

__global__ __launch_bounds__(256) void qkv_hmma_kernel(
    const float* __restrict__ bq, const float* __restrict__ bk,
    const float* __restrict__ bv)
{
    extern __shared__ char smem[];
    const uint32_t smem_base = smem_to_u32(smem);
    const int tid = threadIdx.x, wid = tid >> 5, lane = tid & 31;
    const int z  = blockIdx.z;
    const int m0 = blockIdx.x * 128;
    const int h  = blockIdx.y;
    const int n0 = h * 64;
    const float* bias = (z == 0) ? bq : ((z == 1) ? bk : bv);
    __half* outb      = (z == 0) ? g_qh : ((z == 1) ? g_kh : g_vh);
    const float oscale = (z == 0) ? 0.125f : 1.0f;
    const __nv_bfloat16* Bh = g_wthi + (size_t)z * ND * ND;
    const __nv_bfloat16* Bl = g_wtlo + (size_t)z * ND * ND;

    const int wm = wid >> 1;
    const int wn = wid & 1;
    const int mi = lane >> 3, lr = lane & 7;
    const int ld_row = (mi & 1) * 8 + lr;
    const int ld_col = (mi >> 1) * 8;

    float acc[2][4][4] = {};

    for (int ch = 0; ch < 12; ch++) {
        const int k0 = ch * 64;
        __syncthreads();
        #pragma unroll
        for (int it = 0; it < 4; it++) {
            int lin = it * 256 + tid;
            int row = lin >> 3, c8 = (lin & 7) * 8;
            int m = m0 + row;
            uint4 vh = make_uint4(0, 0, 0, 0), vl = make_uint4(0, 0, 0, 0);
            if (m < NM) {
                vh = *(const uint4*)(g_ahi + (size_t)m * ND + k0 + c8);
                vl = *(const uint4*)(g_alo + (size_t)m * ND + k0 + c8);
            }
            *(uint4*)(smem + SMQ_AHI + (row * LDA + c8) * 2) = vh;
            *(uint4*)(smem + SMQ_ALO + (row * LDA + c8) * 2) = vl;
        }
        #pragma unroll
        for (int it = 0; it < 2; it++) {
            int lin = it * 256 + tid;
            int row = lin >> 3, c8 = (lin & 7) * 8;
            *(uint4*)(smem + SMQ_BHI + (row * LDA + c8) * 2) =
                *(const uint4*)(Bh + (size_t)(n0 + row) * ND + k0 + c8);
            *(uint4*)(smem + SMQ_BLO + (row * LDA + c8) * 2) =
                *(const uint4*)(Bl + (size_t)(n0 + row) * ND + k0 + c8);
        }
        __syncthreads();

        #pragma unroll
        for (int k16 = 0; k16 < 4; k16++) {
            const int kc = k16 * 16 + ld_col;
            uint32_t ah[2][4], al[2][4];
            #pragma unroll
            for (int mf = 0; mf < 2; mf++) {
                uint32_t off =
                    (uint32_t)(((wm * 32 + mf * 16 + ld_row) * LDA + kc) * 2);
                ldsm_x4(ah[mf][0], ah[mf][1], ah[mf][2], ah[mf][3],
                        smem_base + SMQ_AHI + off);
                ldsm_x4(al[mf][0], al[mf][1], al[mf][2], al[mf][3],
                        smem_base + SMQ_ALO + off);
            }
            uint32_t bh[4][2], bl[4][2];
            #pragma unroll
            for (int nf2 = 0; nf2 < 2; nf2++) {
                uint32_t off =
                    (uint32_t)(((wn * 32 + nf2 * 16 + ld_row) * LDA + kc) * 2);
                uint32_t t0, t1, t2, t3;
                ldsm_x4(t0, t1, t2, t3, smem_base + SMQ_BHI + off);
                bh[nf2 * 2 + 0][0] = t0; bh[nf2 * 2 + 0][1] = t2;
                bh[nf2 * 2 + 1][0] = t1; bh[nf2 * 2 + 1][1] = t3;
                ldsm_x4(t0, t1, t2, t3, smem_base + SMQ_BLO + off);
                bl[nf2 * 2 + 0][0] = t0; bl[nf2 * 2 + 0][1] = t2;
                bl[nf2 * 2 + 1][0] = t1; bl[nf2 * 2 + 1][1] = t3;
            }
            #pragma unroll
            for (int mf = 0; mf < 2; mf++)
                #pragma unroll
                for (int nf = 0; nf < 4; nf++) {
                    float* c = acc[mf][nf];
                    mma_16816_bf16(c[0], c[1], c[2], c[3],
                                   ah[mf][0], ah[mf][1], ah[mf][2], ah[mf][3],
                                   bh[nf][0], bh[nf][1]);
                    mma_16816_bf16(c[0], c[1], c[2], c[3],
                                   al[mf][0], al[mf][1], al[mf][2], al[mf][3],
                                   bh[nf][0], bh[nf][1]);
                    mma_16816_bf16(c[0], c[1], c[2], c[3],
                                   ah[mf][0], ah[mf][1], ah[mf][2], ah[mf][3],
                                   bl[nf][0], bl[nf][1]);
                }
        }
    }

    const int er = lane >> 2, ec = (lane & 3) * 2;
    #pragma unroll
    for (int mf = 0; mf < 2; mf++) {
        #pragma unroll
        for (int half_ = 0; half_ < 2; half_++) {
            const int m = m0 + wm * 32 + mf * 16 + er + half_ * 8;
            if (m >= NM) continue;
            const int bb = m / NS, ss = m - bb * NS;
            __half* op = outb + (((size_t)bb * NH + h) * NS + ss) * NHD;
            #pragma unroll
            for (int nf = 0; nf < 4; nf++) {
                const int c = wn * 32 + nf * 8 + ec;
                float ox = (acc[mf][nf][half_ * 2 + 0] + bias[n0 + c + 0]) * oscale;
                float oy = (acc[mf][nf][half_ * 2 + 1] + bias[n0 + c + 1]) * oscale;
                *(uint32_t*)(op + c) = pack_h2(ox, oy);
            }
        }
    }
}

// ---------------------------------------------------------------------------
// Kernel D: flash attention on HMMA fp16. BQ=128 per CTA, 8 warps x 16 rows,
// BK=64. Grid (9, 12, 8). In-register online softmax.
// ---------------------------------------------------------------------------
constexpr int ALD = 72;                       // fp16 row stride
constexpr int SMA_Q = 0;                      // 128 x ALD halfs = 18432 B
constexpr int SMA_K = SMA_Q + 128 * ALD * 2;  // 64 x ALD = 9216 B
constexpr int SMA_V = SMA_K + 64 * ALD * 2;
constexpr int SMA_TOT = SMA_V + 64 * ALD * 2; // 36864 B

__global__ __launch_bounds__(256) void attn_hmma_kernel(
    const float* __restrict__ bias, float* __restrict__ out)
{
    extern __shared__ char smem[];
    const uint32_t smem_base = smem_to_u32(smem);
    const int tid = threadIdx.x, wid = tid >> 5, lane = tid & 31;
    const int q0 = blockIdx.x * 128;
    const int h  = blockIdx.y;
    const int b  = blockIdx.z;

    const __half* Qg = g_qh + ((size_t)(b * NH + h)) * NS * NHD;
    const __half* Kg = g_kh + ((size_t)(b * NH + h)) * NS * NHD;
    const __half* Vg = g_vh + ((size_t)(b * NH + h)) * NS * NHD;
    const float*  Bg = bias + (size_t)h * NS * NS;

    const int mi = lane >> 3, lr = lane & 7;
    const int ld_row = (mi & 1) * 8 + lr;
    const int ld_col = (mi >> 1) * 8;
    const int er = lane >> 2, ec = (lane & 3) * 2;

    // ---- load Q tile to smem, then preload A fragments to registers ----
    #pragma unroll
    for (int it = 0; it < 4; it++) {
        int lin = it * 256 + tid;
        int row = lin >> 3, c8 = (lin & 7) * 8;
        uint4 v = make_uint4(0, 0, 0, 0);
        if (q0 + row < NS)
            v = *(const uint4*)(Qg + (size_t)(q0 + row) * NHD + c8);
        *(uint4*)(smem + SMA_Q + (row * ALD + c8) * 2) = v;
    }
    __syncthreads();
    uint32_t qf[4][4];
    #pragma unroll
    for (int kk = 0; kk < 4; kk++) {
        uint32_t off =
            (uint32_t)(((wid * 16 + ld_row) * ALD + kk * 16 + ld_col) * 2);
        ldsm_x4(qf[kk][0], qf[kk][1], qf[kk][2], qf[kk][3],
                smem_base + SMA_Q + off);
    }

    float ctx[8][4] = {};
    float m_r[2] = {-1e30f, -1e30f};
    float l_r[2] = {0.f, 0.f};
    const int qrow0 = q0 + wid * 16 + er;       // row for frag half 0
    const int qrow1 = qrow0 + 8;
    const float* br0 = Bg + (size_t)((qrow0 < NS) ? qrow0 : (NS - 1)) * NS;
    const float* br1 = Bg + (size_t)((qrow1 < NS) ? qrow1 : (NS - 1)) * NS;

    const int nkt = (NS + 63) / 64;   // 17

    for (int kt = 0; kt < nkt; kt++) {
        const int k0 = kt * 64;
        __syncthreads();
        // ---- load K and V tiles ----
        #pragma unroll
        for (int it = 0; it < 2; it++) {
            int lin = it * 256 + tid;
            int row = lin >> 3, c8 = (lin & 7) * 8;
            uint4 kv = make_uint4(0, 0, 0, 0), vv = make_uint4(0, 0, 0, 0);
            if (k0 + row < NS) {
                kv = *(const uint4*)(Kg + (size_t)(k0 + row) * NHD + c8);
                vv = *(const uint4*)(Vg + (size_t)(k0 + row) * NHD + c8);
            }
            *(uint4*)(smem + SMA_K + (row * ALD + c8) * 2) = kv;
            *(uint4*)(smem + SMA_V + (row * ALD + c8) * 2) = vv;
        }
        __syncthreads();

        // ---- S = Q K^T : 8 n-frags x 4 k16 ----
        float sf[8][4];
        #pragma unroll
        for (int nf = 0; nf < 8; nf++)
            #pragma unroll
            for (int c = 0; c < 4; c++) sf[nf][c] = 0.f;
        #pragma unroll
        for (int kk = 0; kk < 4; kk++) {
            uint32_t bfr[8][2];
            #pragma unroll
            for (int nf2 = 0; nf2 < 4; nf2++) {
                uint32_t off = (uint32_t)(
                    ((nf2 * 16 + ld_row) * ALD + kk * 16 + ld_col) * 2);
                uint32_t t0, t1, t2, t3;
                ldsm_x4(t0, t1, t2, t3, smem_base + SMA_K + off);
                bfr[nf2 * 2 + 0][0] = t0; bfr[nf2 * 2 + 0][1] = t2;
                bfr[nf2 * 2 + 1][0] = t1; bfr[nf2 * 2 + 1][1] = t3;
            }
            #pragma unroll
            for (int nf = 0; nf < 8; nf++)
                mma_16816_f16(sf[nf][0], sf[nf][1], sf[nf][2], sf[nf][3],
                              qf[kk][0], qf[kk][1], qf[kk][2], qf[kk][3],
                              bfr[nf][0], bfr[nf][1]);
        }

        // ---- add bias, mask, online softmax (in registers) ----
        #pragma unroll
        for (int r = 0; r < 2; r++) {
            const float* br = r ? br1 : br0;
            float mx = m_r[r];
            #pragma unroll
            for (int nf = 0; nf < 8; nf++) {
                #pragma unroll
                for (int c = 0; c < 2; c++) {
                    const int kcol = k0 + nf * 8 + ec + c;
                    float s = (kcol < NS)
                        ? (sf[nf][r * 2 + c] + __ldg(br + kcol))
                        : -1e30f;
                    sf[nf][r * 2 + c] = s;
                    mx = fmaxf(mx, s);
                }
            }
            mx = fmaxf(mx, __shfl_xor_sync(0xffffffffu, mx, 1));
            mx = fmaxf(mx, __shfl_xor_sync(0xffffffffu, mx, 2));
            const float scale_f = __expf(m_r[r] - mx);
            float l = l_r[r] * scale_f;
            #pragma unroll
            for (int nf = 0; nf < 8; nf++) {
                #pragma unroll
                for (int c = 0; c < 2; c++) {
                    float p = __expf(sf[nf][r * 2 + c] - mx);
                    sf[nf][r * 2 + c] = p;
                    l += p;
                }
            }
            m_r[r] = mx;
            l_r[r] = l;
            #pragma unroll
            for (int df = 0; df < 8; df++) {
                ctx[df][r * 2 + 0] *= scale_f;
                ctx[df][r * 2 + 1] *= scale_f;
            }
        }

        // ---- pack P into A fragments (register-direct) ----
        uint32_t pa[4][4];
        #pragma unroll
        for (int kk = 0; kk < 4; kk++) {
            pa[kk][0] = pack_h2(sf[2 * kk + 0][0], sf[2 * kk + 0][1]);
            pa[kk][1] = pack_h2(sf[2 * kk + 0][2], sf[2 * kk + 0][3]);
            pa[kk][2] = pack_h2(sf[2 * kk + 1][0], sf[2 * kk + 1][1]);
            pa[kk][3] = pack_h2(sf[2 * kk + 1][2], sf[2 * kk + 1][3]);
        }

        // ---- ctx += P V : B frags via ldmatrix.trans on V ----
        const int g = lane >> 3;
        #pragma unroll
        for (int kk = 0; kk < 4; kk++) {
            uint32_t vb[8][2];
            #pragma unroll
            for (int df2 = 0; df2 < 4; df2++) {
                uint32_t off = (uint32_t)(
                    ((kk * 16 + (g & 1) * 8 + (lane & 7)) * ALD
                     + df2 * 16 + (g >> 1) * 8) * 2);
                uint32_t t0, t1, t2, t3;
                ldsm_x4_trans(t0, t1, t2, t3, smem_base + SMA_V + off);
                vb[df2 * 2 + 0][0] = t0; vb[df2 * 2 + 0][1] = t1;
                vb[df2 * 2 + 1][0] = t2; vb[df2 * 2 + 1][1] = t3;
            }
            #pragma unroll
            for (int df = 0; df < 8; df++)
                mma_16816_f16(ctx[df][0], ctx[df][1], ctx[df][2], ctx[df][3],
                              pa[kk][0], pa[kk][1], pa[kk][2], pa[kk][3],
                              vb[df][0], vb[df][1]);
        }
    }

    // ---- epilogue: reduce l across quad, normalize, write fp32 ----
    #pragma unroll
    for (int r = 0; r < 2; r++) {
        float l = l_r[r];
        l += __shfl_xor_sync(0xffffffffu, l, 1);
        l += __shfl_xor_sync(0xffffffffu, l, 2);
        l_r[r] = l;
    }
    #pragma unroll
    for (int r = 0; r < 2; r++) {
        const int q = r ? qrow1 : qrow0;
        if (q >= NS) continue;
        const float inv = 1.0f / l_r[r];
        float* op = out + ((size_t)b * NS + q) * ND + h * NHD;
        #pragma unroll
        for (int df = 0; df < 8; df++) {
            float2 o;
            o.x = ctx[df][r * 2 + 0] * inv;
            o.y = ctx[df][r * 2 + 1] * inv;
            *(float2*)(op + df * 8 + ec) = o;
        }
    }
}

// ---------------------------------------------------------------------------
extern "C" void kernel_launch(void* const* d_in, const int* in_sizes, int n_in,
                              void* d_out, int out_size)
{
    const float* hs = (const float*)d_in[0];
    const float* rb = (const float*)d_in[1];
    const float* Wq = (const float*)d_in[2];
    const float* bq = (const float*)d_in[3];
    const float* Wk = (const float*)d_in[4];
    const float* bk = (const float*)d_in[5];
    const float* Wv = (const float*)d_in[6];
    const float* bv = (const float*)d_in[7];
    float* out = (float*)d_out;

    aconv_kernel<<<(int)(((size_t)NM * ND / 4 + 255) / 256), 256>>>(hs);
    dim3 gw(ND / 32, ND / 32, 3);
    wtrans_kernel<<<gw, dim3(32, 8)>>>(Wq, Wk, Wv);

    cudaFuncSetAttribute(qkv_hmma_kernel,
                         cudaFuncAttributeMaxDynamicSharedMemorySize, SMQ_TOT);
    dim3 g1((NM + 127) / 128, NH, 3);
    qkv_hmma_kernel<<<g1, 256, SMQ_TOT>>>(bq, bk, bv);

    cudaFuncSetAttribute(attn_hmma_kernel,
                         cudaFuncAttributeMaxDynamicSharedMemorySize, SMA_TOT);
    dim3 g2((NS + 127) / 128, NH, NB);
    attn_hmma_kernel<<<g2, 256, SMA_TOT>>>(rb, out);
}

// round 7
// speedup vs baseline: 4.3623x; 1.1265x over previous
#include <cuda_runtime.h>
#include <cuda_bf16.h>
#include <cuda_fp16.h>
#include <cstdint>

// Problem constants
constexpr int NB  = 8;
constexpr int NS  = 1025;
constexpr int ND  = 768;
constexpr int NH  = 12;
constexpr int NHD = 64;
constexpr int NM  = NB * NS;      // 8200

// Scratch
__device__ __half g_qh[(size_t)NB * NH * NS * NHD];   // q * 0.125, fp16
__device__ __half g_kh[(size_t)NB * NH * NS * NHD];
__device__ __half g_vh[(size_t)NB * NH * NS * NHD];
__device__ __nv_bfloat16 g_ahi[(size_t)NM * ND];
__device__ __nv_bfloat16 g_alo[(size_t)NM * ND];
__device__ __nv_bfloat16 g_wthi[(size_t)3 * ND * ND];   // transposed: [n][k]
__device__ __nv_bfloat16 g_wtlo[(size_t)3 * ND * ND];

// ---------------------------------------------------------------------------
// PTX helpers
// ---------------------------------------------------------------------------
__device__ __forceinline__ uint32_t smem_to_u32(const void* p) {
    uint32_t a;
    asm("{ .reg .u64 t; cvta.to.shared.u64 t, %1; cvt.u32.u64 %0, t; }"
        : "=r"(a) : "l"(p));
    return a;
}
__device__ __forceinline__ void ldsm_x4(uint32_t& r0, uint32_t& r1,
                                        uint32_t& r2, uint32_t& r3,
                                        uint32_t addr) {
    asm volatile("ldmatrix.sync.aligned.m8n8.x4.shared.b16 {%0,%1,%2,%3}, [%4];"
                 : "=r"(r0), "=r"(r1), "=r"(r2), "=r"(r3) : "r"(addr));
}
__device__ __forceinline__ void ldsm_x4_trans(uint32_t& r0, uint32_t& r1,
                                              uint32_t& r2, uint32_t& r3,
                                              uint32_t addr) {
    asm volatile("ldmatrix.sync.aligned.m8n8.x4.trans.shared.b16 {%0,%1,%2,%3}, [%4];"
                 : "=r"(r0), "=r"(r1), "=r"(r2), "=r"(r3) : "r"(addr));
}
__device__ __forceinline__ void mma_16816_bf16(
    float& c0, float& c1, float& c2, float& c3,
    uint32_t a0, uint32_t a1, uint32_t a2, uint32_t a3,
    uint32_t b0, uint32_t b1) {
    asm volatile(
        "mma.sync.aligned.m16n8k16.row.col.f32.bf16.bf16.f32 "
        "{%0,%1,%2,%3}, {%4,%5,%6,%7}, {%8,%9}, {%0,%1,%2,%3};"
        : "+f"(c0), "+f"(c1), "+f"(c2), "+f"(c3)
        : "r"(a0), "r"(a1), "r"(a2), "r"(a3), "r"(b0), "r"(b1));
}
__device__ __forceinline__ void mma_16816_f16(
    float& c0, float& c1, float& c2, float& c3,
    uint32_t a0, uint32_t a1, uint32_t a2, uint32_t a3,
    uint32_t b0, uint32_t b1) {
    asm volatile(
        "mma.sync.aligned.m16n8k16.row.col.f32.f16.f16.f32 "
        "{%0,%1,%2,%3}, {%4,%5,%6,%7}, {%8,%9}, {%0,%1,%2,%3};"
        : "+f"(c0), "+f"(c1), "+f"(c2), "+f"(c3)
        : "r"(a0), "r"(a1), "r"(a2), "r"(a3), "r"(b0), "r"(b1));
}
__device__ __forceinline__ uint32_t pack_h2(float lo, float hi) {
    uint32_t r;
    asm("cvt.rn.f16x2.f32 %0, %1, %2;" : "=r"(r) : "f"(hi), "f"(lo));
    return r;
}
__device__ __forceinline__ void cp_async16(uint32_t dst, const void* src,
                                           int szbytes) {
    asm volatile("cp.async.cg.shared.global [%0], [%1], 16, %2;"
                 :: "r"(dst), "l"(src), "r"(szbytes));
}
#define CP_COMMIT() asm volatile("cp.async.commit_group;" ::: "memory")
#define CP_WAIT(n)  asm volatile("cp.async.wait_group %0;" :: "n"(n) : "memory")

// ---------------------------------------------------------------------------
// Kernel A: split hidden_states fp32 -> (hi, lo) bf16
// ---------------------------------------------------------------------------
__global__ __launch_bounds__(256) void aconv_kernel(const float* __restrict__ A)
{
    size_t i = ((size_t)blockIdx.x * 256 + threadIdx.x) * 4;
    if (i >= (size_t)NM * ND) return;
    float4 v = *(const float4*)(A + i);
    __nv_bfloat16 h0 = __float2bfloat16(v.x), h1 = __float2bfloat16(v.y);
    __nv_bfloat16 h2 = __float2bfloat16(v.z), h3 = __float2bfloat16(v.w);
    __nv_bfloat16 l0 = __float2bfloat16(v.x - __bfloat162float(h0));
    __nv_bfloat16 l1 = __float2bfloat16(v.y - __bfloat162float(h1));
    __nv_bfloat16 l2 = __float2bfloat16(v.z - __bfloat162float(h2));
    __nv_bfloat16 l3 = __float2bfloat16(v.w - __bfloat162float(h3));
    *(__nv_bfloat162*)(g_ahi + i)     = __halves2bfloat162(h0, h1);
    *(__nv_bfloat162*)(g_ahi + i + 2) = __halves2bfloat162(h2, h3);
    *(__nv_bfloat162*)(g_alo + i)     = __halves2bfloat162(l0, l1);
    *(__nv_bfloat162*)(g_alo + i + 2) = __halves2bfloat162(l2, l3);
}

// ---------------------------------------------------------------------------
// Kernel B: transpose + split W fp32 [K,N] -> Wt (hi,lo) bf16 [N,K]
// ---------------------------------------------------------------------------
__global__ __launch_bounds__(256) void wtrans_kernel(
    const float* __restrict__ Wq, const float* __restrict__ Wk,
    const float* __restrict__ Wv)
{
    __shared__ float t[32][33];
    const int z = blockIdx.z;
    const float* W = (z == 0) ? Wq : ((z == 1) ? Wk : Wv);
    __nv_bfloat16* hi = g_wthi + (size_t)z * ND * ND;
    __nv_bfloat16* lo = g_wtlo + (size_t)z * ND * ND;
    const int n0 = blockIdx.x * 32, k0 = blockIdx.y * 32;
    const int tx = threadIdx.x, ty = threadIdx.y;   // (32, 8)
    #pragma unroll
    for (int i = 0; i < 32; i += 8)
        t[ty + i][tx] = W[(size_t)(k0 + ty + i) * ND + n0 + tx];
    __syncthreads();
    #pragma unroll
    for (int i = 0; i < 32; i += 8) {
        float v = t[tx][ty + i];
        __nv_bfloat16 h = __float2bfloat16(v);
        hi[(size_t)(n0 + ty + i) * ND + k0 + tx] = h;
        lo[(size_t)(n0 + ty + i) * ND + k0 + tx] =
            __float2bfloat16(v - __bfloat162float(h));
    }
}

// ---------------------------------------------------------------------------
// Kernel C: QKV projection HMMA (bf16 3-way split, fp32 accum), fp16 output.
// CTA tile 128x64, BK=64, 8 warps 4x2. Grid (65, 12, 3). Q scaled by 0.125.
// ---------------------------------------------------------------------------
constexpr int LDA = 72;
constexpr int SMQ_AHI = 0;
constexpr int SMQ_ALO = SMQ_AHI + 128 * LDA * 2;
constexpr int SMQ_BHI = SMQ_ALO + 128 * LDA * 2;
constexpr int SMQ_BLO = SMQ_BHI + 64 * LDA * 2;
constexpr int SMQ_TOT = SMQ_BLO + 64 * LDA * 2;    // 55296 B

__global__ __launch_bounds__(256, 2) void qkv_hmma_kernel(
    const float* __restrict__ bq, const float* __restrict__ bk,
    const float* __restrict__ bv)
{
    extern __shared__ char smem[];
    const uint32_t smem_base = smem_to_u32(smem);
    const int tid = threadIdx.x, wid = tid >> 5, lane = tid & 31;
    const int z  = blockIdx.z;
    const int m0 = blockIdx.x * 128;
    const int h  = blockIdx.y;
    const int n0 = h * 64;
    const float* bias = (z == 0) ? bq : ((z == 1) ? bk : bv);
    __half* outb      = (z == 0) ? g_qh : ((z == 1) ? g_kh : g_vh);
    const float oscale = (z == 0) ? 0.125f : 1.0f;
    const __nv_bfloat16* Bh = g_wthi + (size_t)z * ND * ND;
    const __nv_bfloat16* Bl = g_wtlo + (size_t)z * ND * ND;

    const int wm = wid >> 1;
    const int wn = wid & 1;
    const int mi = lane >> 3, lr = lane & 7;
    const int ld_row = (mi & 1) * 8 + lr;
    const int ld_col = (mi >> 1) * 8;

    float acc[2][4][4] = {};

    for (int ch = 0; ch < 12; ch++) {
        const int k0 = ch * 64;
        __syncthreads();
        // A tiles via cp.async (zero-fill tail via src-size 0, clamped addr)
        #pragma unroll
        for (int it = 0; it < 4; it++) {
            int lin = it * 256 + tid;
            int row = lin >> 3, c8 = (lin & 7) * 8;
            int m = m0 + row;
            int sz = (m < NM) ? 16 : 0;
            int mc = (m < NM) ? m : (NM - 1);
            uint32_t so = (uint32_t)((row * LDA + c8) * 2);
            cp_async16(smem_base + SMQ_AHI + so,
                       g_ahi + (size_t)mc * ND + k0 + c8, sz);
            cp_async16(smem_base + SMQ_ALO + so,
                       g_alo + (size_t)mc * ND + k0 + c8, sz);
        }
        // B tiles (always in-bounds)
        #pragma unroll
        for (int it = 0; it < 2; it++) {
            int lin = it * 256 + tid;
            int row = lin >> 3, c8 = (lin & 7) * 8;
            uint32_t so = (uint32_t)((row * LDA + c8) * 2);
            cp_async16(smem_base + SMQ_BHI + so,
                       Bh + (size_t)(n0 + row) * ND + k0 + c8, 16);
            cp_async16(smem_base + SMQ_BLO + so,
                       Bl + (size_t)(n0 + row) * ND + k0 + c8, 16);
        }
        CP_COMMIT();
        CP_WAIT(0);
        __syncthreads();

        #pragma unroll
        for (int k16 = 0; k16 < 4; k16++) {
            const int kc = k16 * 16 + ld_col;
            uint32_t ah[2][4], al[2][4];
            #pragma unroll
            for (int mf = 0; mf < 2; mf++) {
                uint32_t off =
                    (uint32_t)(((wm * 32 + mf * 16 + ld_row) * LDA + kc) * 2);
                ldsm_x4(ah[mf][0], ah[mf][1], ah[mf][2], ah[mf][3],
                        smem_base + SMQ_AHI + off);
                ldsm_x4(al[mf][0], al[mf][1], al[mf][2], al[mf][3],
                        smem_base + SMQ_ALO + off);
            }
            uint32_t bh[4][2], bl[4][2];
            #pragma unroll
            for (int nf2 = 0; nf2 < 2; nf2++) {
                uint32_t off =
                    (uint32_t)(((wn * 32 + nf2 * 16 + ld_row) * LDA + kc) * 2);
                uint32_t t0, t1, t2, t3;
                ldsm_x4(t0, t1, t2, t3, smem_base + SMQ_BHI + off);
                bh[nf2 * 2 + 0][0] = t0; bh[nf2 * 2 + 0][1] = t2;
                bh[nf2 * 2 + 1][0] = t1; bh[nf2 * 2 + 1][1] = t3;
                ldsm_x4(t0, t1, t2, t3, smem_base + SMQ_BLO + off);
                bl[nf2 * 2 + 0][0] = t0; bl[nf2 * 2 + 0][1] = t2;
                bl[nf2 * 2 + 1][0] = t1; bl[nf2 * 2 + 1][1] = t3;
            }
            #pragma unroll
            for (int mf = 0; mf < 2; mf++)
                #pragma unroll
                for (int nf = 0; nf < 4; nf++) {
                    float* c = acc[mf][nf];
                    mma_16816_bf16(c[0], c[1], c[2], c[3],
                                   ah[mf][0], ah[mf][1], ah[mf][2], ah[mf][3],
                                   bh[nf][0], bh[nf][1]);
                    mma_16816_bf16(c[0], c[1], c[2], c[3],
                                   al[mf][0], al[mf][1], al[mf][2], al[mf][3],
                                   bh[nf][0], bh[nf][1]);
                    mma_16816_bf16(c[0], c[1], c[2], c[3],
                                   ah[mf][0], ah[mf][1], ah[mf][2], ah[mf][3],
                                   bl[nf][0], bl[nf][1]);
                }
        }
    }

    const int er = lane >> 2, ec = (lane & 3) * 2;
    #pragma unroll
    for (int mf = 0; mf < 2; mf++) {
        #pragma unroll
        for (int half_ = 0; half_ < 2; half_++) {
            const int m = m0 + wm * 32 + mf * 16 + er + half_ * 8;
            if (m >= NM) continue;
            const int bb = m / NS, ss = m - bb * NS;
            __half* op = outb + (((size_t)bb * NH + h) * NS + ss) * NHD;
            #pragma unroll
            for (int nf = 0; nf < 4; nf++) {
                const int c = wn * 32 + nf * 8 + ec;
                float ox = (acc[mf][nf][half_ * 2 + 0] + bias[n0 + c + 0]) * oscale;
                float oy = (acc[mf][nf][half_ * 2 + 1] + bias[n0 + c + 1]) * oscale;
                *(uint32_t*)(op + c) = pack_h2(ox, oy);
            }
        }
    }
}

// ---------------------------------------------------------------------------
// Kernel D: flash attention on HMMA fp16. BQ=128 per CTA, 8 warps x 16 rows,
// BK=64, 2-stage cp.async K/V pipeline. Grid (9, 12, 8).
// ---------------------------------------------------------------------------
constexpr int ALD = 72;                        // fp16 row stride
constexpr int STG = 64 * ALD * 2;              // one K or V stage: 9216 B
constexpr int SMA_Q = 0;                       // 128 x ALD = 18432 B
constexpr int SMA_K = SMA_Q + 128 * ALD * 2;   // 2 stages
constexpr int SMA_V = SMA_K + 2 * STG;         // 2 stages
constexpr int SMA_TOT = SMA_V + 2 * STG;       // 55296 B

__global__ __launch_bounds__(256, 2) void attn_hmma_kernel(
    const float* __restrict__ bias, float* __restrict__ out)
{
    extern __shared__ char smem[];
    const uint32_t smem_base = smem_to_u32(smem);
    const int tid = threadIdx.x, wid = tid >> 5, lane = tid & 31;
    const int q0 = blockIdx.x * 128;
    const int h  = blockIdx.y;
    const int b  = blockIdx.z;

    const __half* Qg = g_qh + ((size_t)(b * NH + h)) * NS * NHD;
    const __half* Kg = g_kh + ((size_t)(b * NH + h)) * NS * NHD;
    const __half* Vg = g_vh + ((size_t)(b * NH + h)) * NS * NHD;
    const float*  Bg = bias + (size_t)h * NS * NS;

    const int mi = lane >> 3, lr = lane & 7;
    const int ld_row = (mi & 1) * 8 + lr;
    const int ld_col = (mi >> 1) * 8;
    const int er = lane >> 2, ec = (lane & 3) * 2;

    const int nkt = (NS + 63) / 64;   // 17

    // issue K/V loads for tile kt into stage kt&1
    auto load_kv = [&](int kt) {
        const int st = kt & 1;
        #pragma unroll
        for (int it = 0; it < 2; it++) {
            int lin = it * 256 + tid;
            int row = lin >> 3, c8 = (lin & 7) * 8;
            int gr = kt * 64 + row;
            int sz = (gr < NS) ? 16 : 0;
            int grc = (gr < NS) ? gr : (NS - 1);
            uint32_t so = (uint32_t)((row * ALD + c8) * 2);
            cp_async16(smem_base + SMA_K + st * STG + so,
                       Kg + (size_t)grc * NHD + c8, sz);
            cp_async16(smem_base + SMA_V + st * STG + so,
                       Vg + (size_t)grc * NHD + c8, sz);
        }
        CP_COMMIT();
    };

    // prefetch tile 0 while loading Q
    load_kv(0);

    #pragma unroll
    for (int it = 0; it < 4; it++) {
        int lin = it * 256 + tid;
        int row = lin >> 3, c8 = (lin & 7) * 8;
        int sz = (q0 + row < NS) ? 16 : 0;
        int qc = (q0 + row < NS) ? (q0 + row) : (NS - 1);
        cp_async16(smem_base + SMA_Q + (uint32_t)((row * ALD + c8) * 2),
                   Qg + (size_t)qc * NHD + c8, sz);
    }
    CP_COMMIT();
    CP_WAIT(0);
    __syncthreads();

    uint32_t qf[4][4];
    #pragma unroll
    for (int kk = 0; kk < 4; kk++) {
        uint32_t off =
            (uint32_t)(((wid * 16 + ld_row) * ALD + kk * 16 + ld_col) * 2);
        ldsm_x4(qf[kk][0], qf[kk][1], qf[kk][2], qf[kk][3],
                smem_base + SMA_Q + off);
    }

    float ctx[8][4] = {};
    float m_r[2] = {-1e30f, -1e30f};
    float l_r[2] = {0.f, 0.f};
    const int qrow0 = q0 + wid * 16 + er;
    const int qrow1 = qrow0 + 8;
    const float* br0 = Bg + (size_t)((qrow0 < NS) ? qrow0 : (NS - 1)) * NS;
    const float* br1 = Bg + (size_t)((qrow1 < NS) ? qrow1 : (NS - 1)) * NS;

    for (int kt = 0; kt < nkt; kt++) {
        const int k0 = kt * 64;
        const int st = kt & 1;
        __syncthreads();   // all warps done reading stage (kt+1)&1 from iter kt-1
        if (kt + 1 < nkt) {
            load_kv(kt + 1);
            CP_WAIT(1);    // stage kt complete; kt+1 in flight
        } else {
            CP_WAIT(0);
        }
        __syncthreads();

        // ---- S = Q K^T ----
        float sf[8][4];
        #pragma unroll
        for (int nf = 0; nf < 8; nf++)
            #pragma unroll
            for (int c = 0; c < 4; c++) sf[nf][c] = 0.f;
        #pragma unroll
        for (int kk = 0; kk < 4; kk++) {
            uint32_t bfr[8][2];
            #pragma unroll
            for (int nf2 = 0; nf2 < 4; nf2++) {
                uint32_t off = (uint32_t)(
                    ((nf2 * 16 + ld_row) * ALD + kk * 16 + ld_col) * 2);
                uint32_t t0, t1, t2, t3;
                ldsm_x4(t0, t1, t2, t3, smem_base + SMA_K + st * STG + off);
                bfr[nf2 * 2 + 0][0] = t0; bfr[nf2 * 2 + 0][1] = t2;
                bfr[nf2 * 2 + 1][0] = t1; bfr[nf2 * 2 + 1][1] = t3;
            }
            #pragma unroll
            for (int nf = 0; nf < 8; nf++)
                mma_16816_f16(sf[nf][0], sf[nf][1], sf[nf][2], sf[nf][3],
                              qf[kk][0], qf[kk][1], qf[kk][2], qf[kk][3],
                              bfr[nf][0], bfr[nf][1]);
        }

        // ---- bias + mask + online softmax (registers) ----
        #pragma unroll
        for (int r = 0; r < 2; r++) {
            const float* br = r ? br1 : br0;
            float mx = m_r[r];
            #pragma unroll
            for (int nf = 0; nf < 8; nf++) {
                #pragma unroll
                for (int c = 0; c < 2; c++) {
                    const int kcol = k0 + nf * 8 + ec + c;
                    float s = (kcol < NS)
                        ? (sf[nf][r * 2 + c] + __ldg(br + kcol))
                        : -1e30f;
                    sf[nf][r * 2 + c] = s;
                    mx = fmaxf(mx, s);
                }
            }
            mx = fmaxf(mx, __shfl_xor_sync(0xffffffffu, mx, 1));
            mx = fmaxf(mx, __shfl_xor_sync(0xffffffffu, mx, 2));
            const float scale_f = __expf(m_r[r] - mx);
            float l = l_r[r] * scale_f;
            #pragma unroll
            for (int nf = 0; nf < 8; nf++) {
                #pragma unroll
                for (int c = 0; c < 2; c++) {
                    float p = __expf(sf[nf][r * 2 + c] - mx);
                    sf[nf][r * 2 + c] = p;
                    l += p;
                }
            }
            m_r[r] = mx;
            l_r[r] = l;
            #pragma unroll
            for (int df = 0; df < 8; df++) {
                ctx[df][r * 2 + 0] *= scale_f;
                ctx[df][r * 2 + 1] *= scale_f;
            }
        }

        // ---- pack P into A frags (register-direct) ----
        uint32_t pa[4][4];
        #pragma unroll
        for (int kk = 0; kk < 4; kk++) {
            pa[kk][0] = pack_h2(sf[2 * kk + 0][0], sf[2 * kk + 0][1]);
            pa[kk][1] = pack_h2(sf[2 * kk + 0][2], sf[2 * kk + 0][3]);
            pa[kk][2] = pack_h2(sf[2 * kk + 1][0], sf[2 * kk + 1][1]);
            pa[kk][3] = pack_h2(sf[2 * kk + 1][2], sf[2 * kk + 1][3]);
        }

        // ---- ctx += P V ----
        const int g = lane >> 3;
        #pragma unroll
        for (int kk = 0; kk < 4; kk++) {
            uint32_t vb[8][2];
            #pragma unroll
            for (int df2 = 0; df2 < 4; df2++) {
                uint32_t off = (uint32_t)(
                    ((kk * 16 + (g & 1) * 8 + (lane & 7)) * ALD
                     + df2 * 16 + (g >> 1) * 8) * 2);
                uint32_t t0, t1, t2, t3;
                ldsm_x4_trans(t0, t1, t2, t3,
                              smem_base + SMA_V + st * STG + off);
                vb[df2 * 2 + 0][0] = t0; vb[df2 * 2 + 0][1] = t1;
                vb[df2 * 2 + 1][0] = t2; vb[df2 * 2 + 1][1] = t3;
            }
            #pragma unroll
            for (int df = 0; df < 8; df++)
                mma_16816_f16(ctx[df][0], ctx[df][1], ctx[df][2], ctx[df][3],
                              pa[kk][0], pa[kk][1], pa[kk][2], pa[kk][3],
                              vb[df][0], vb[df][1]);
        }
    }

    // ---- epilogue ----
    #pragma unroll
    for (int r = 0; r < 2; r++) {
        float l = l_r[r];
        l += __shfl_xor_sync(0xffffffffu, l, 1);
        l += __shfl_xor_sync(0xffffffffu, l, 2);
        l_r[r] = l;
    }
    #pragma unroll
    for (int r = 0; r < 2; r++) {
        const int q = r ? qrow1 : qrow0;
        if (q >= NS) continue;
        const float inv = 1.0f / l_r[r];
        float* op = out + ((size_t)b * NS + q) * ND + h * NHD;
        #pragma unroll
        for (int df = 0; df < 8; df++) {
            float2 o;
            o.x = ctx[df][r * 2 + 0] * inv;
            o.y = ctx[df][r * 2 + 1] * inv;
            *(float2*)(op + df * 8 + ec) = o;
        }
    }
}

// ---------------------------------------------------------------------------
extern "C" void kernel_launch(void* const* d_in, const int* in_sizes, int n_in,
                              void* d_out, int out_size)
{
    const float* hs = (const float*)d_in[0];
    const float* rb = (const float*)d_in[1];
    const float* Wq = (const float*)d_in[2];
    const float* bq = (const float*)d_in[3];
    const float* Wk = (const float*)d_in[4];
    const float* bk = (const float*)d_in[5];
    const float* Wv = (const float*)d_in[6];
    const float* bv = (const float*)d_in[7];
    float* out = (float*)d_out;

    aconv_kernel<<<(int)(((size_t)NM * ND / 4 + 255) / 256), 256>>>(hs);
    dim3 gw(ND / 32, ND / 32, 3);
    wtrans_kernel<<<gw, dim3(32, 8)>>>(Wq, Wk, Wv);

    cudaFuncSetAttribute(qkv_hmma_kernel,
                         cudaFuncAttributeMaxDynamicSharedMemorySize, SMQ_TOT);
    dim3 g1((NM + 127) / 128, NH, 3);
    qkv_hmma_kernel<<<g1, 256, SMQ_TOT>>>(bq, bk, bv);

    cudaFuncSetAttribute(attn_hmma_kernel,
                         cudaFuncAttributeMaxDynamicSharedMemorySize, SMA_TOT);
    dim3 g2((NS + 127) / 128, NH, NB);
    attn_hmma_kernel<<<g2, 256, SMA_TOT>>>(rb, out);
}

// round 9
// speedup vs baseline: 4.7424x; 1.0871x over previous
#include <cuda_runtime.h>
#include <cuda_bf16.h>
#include <cuda_fp16.h>
#include <cstdint>

// Problem constants
constexpr int NB  = 8;
constexpr int NS  = 1025;
constexpr int ND  = 768;
constexpr int NH  = 12;
constexpr int NHD = 64;
constexpr int NM  = NB * NS;      // 8200

// Scratch
__device__ __half g_qh[(size_t)NB * NH * NS * NHD];   // q * 0.125, fp16
__device__ __half g_kh[(size_t)NB * NH * NS * NHD];
__device__ __half g_vh[(size_t)NB * NH * NS * NHD];
__device__ __half g_ahi[(size_t)NM * ND];             // hidden hi (fp16)
__device__ __half g_alo[(size_t)NM * ND];             // hidden residual (fp16)
__device__ __half g_wt[(size_t)3 * ND * ND];          // W transposed [n][k], fp16

// ---------------------------------------------------------------------------
// PTX helpers
// ---------------------------------------------------------------------------
__device__ __forceinline__ uint32_t smem_to_u32(const void* p) {
    uint32_t a;
    asm("{ .reg .u64 t; cvta.to.shared.u64 t, %1; cvt.u32.u64 %0, t; }"
        : "=r"(a) : "l"(p));
    return a;
}
__device__ __forceinline__ void ldsm_x4(uint32_t& r0, uint32_t& r1,
                                        uint32_t& r2, uint32_t& r3,
                                        uint32_t addr) {
    asm volatile("ldmatrix.sync.aligned.m8n8.x4.shared.b16 {%0,%1,%2,%3}, [%4];"
                 : "=r"(r0), "=r"(r1), "=r"(r2), "=r"(r3) : "r"(addr));
}
__device__ __forceinline__ void ldsm_x4_trans(uint32_t& r0, uint32_t& r1,
                                              uint32_t& r2, uint32_t& r3,
                                              uint32_t addr) {
    asm volatile("ldmatrix.sync.aligned.m8n8.x4.trans.shared.b16 {%0,%1,%2,%3}, [%4];"
                 : "=r"(r0), "=r"(r1), "=r"(r2), "=r"(r3) : "r"(addr));
}
__device__ __forceinline__ void mma_16816_f16(
    float& c0, float& c1, float& c2, float& c3,
    uint32_t a0, uint32_t a1, uint32_t a2, uint32_t a3,
    uint32_t b0, uint32_t b1) {
    asm volatile(
        "mma.sync.aligned.m16n8k16.row.col.f32.f16.f16.f32 "
        "{%0,%1,%2,%3}, {%4,%5,%6,%7}, {%8,%9}, {%0,%1,%2,%3};"
        : "+f"(c0), "+f"(c1), "+f"(c2), "+f"(c3)
        : "r"(a0), "r"(a1), "r"(a2), "r"(a3), "r"(b0), "r"(b1));
}
__device__ __forceinline__ uint32_t pack_h2(float lo, float hi) {
    uint32_t r;
    asm("cvt.rn.f16x2.f32 %0, %1, %2;" : "=r"(r) : "f"(hi), "f"(lo));
    return r;
}
__device__ __forceinline__ void cp_async16(uint32_t dst, const void* src,
                                           int szbytes) {
    asm volatile("cp.async.cg.shared.global [%0], [%1], 16, %2;"
                 :: "r"(dst), "l"(src), "r"(szbytes));
}
#define CP_COMMIT() asm volatile("cp.async.commit_group;" ::: "memory")
#define CP_WAIT(n)  asm volatile("cp.async.wait_group %0;" :: "n"(n) : "memory")

// ---------------------------------------------------------------------------
// Kernel A: split hidden_states fp32 -> (hi, lo) fp16
// ---------------------------------------------------------------------------
__global__ __launch_bounds__(256) void aconv_kernel(const float* __restrict__ A)
{
    size_t i = ((size_t)blockIdx.x * 256 + threadIdx.x) * 4;
    if (i >= (size_t)NM * ND) return;
    float4 v = *(const float4*)(A + i);
    __half h0 = __float2half(v.x), h1 = __float2half(v.y);
    __half h2 = __float2half(v.z), h3 = __float2half(v.w);
    __half l0 = __float2half(v.x - __half2float(h0));
    __half l1 = __float2half(v.y - __half2float(h1));
    __half l2 = __float2half(v.z - __half2float(h2));
    __half l3 = __float2half(v.w - __half2float(h3));
    *(__half2*)(g_ahi + i)     = __halves2half2(h0, h1);
    *(__half2*)(g_ahi + i + 2) = __halves2half2(h2, h3);
    *(__half2*)(g_alo + i)     = __halves2half2(l0, l1);
    *(__half2*)(g_alo + i + 2) = __halves2half2(l2, l3);
}

// ---------------------------------------------------------------------------
// Kernel B: transpose W fp32 [K,N] -> Wt fp16 [N,K]
// ---------------------------------------------------------------------------
__global__ __launch_bounds__(256) void wtrans_kernel(
    const float* __restrict__ Wq, const float* __restrict__ Wk,
    const float* __restrict__ Wv)
{
    __shared__ float t[32][33];
    const int z = blockIdx.z;
    const float* W = (z == 0) ? Wq : ((z == 1) ? Wk : Wv);
    __half* wt = g_wt + (size_t)z * ND * ND;
    const int n0 = blockIdx.x * 32, k0 = blockIdx.y * 32;
    const int tx = threadIdx.x, ty = threadIdx.y;   // (32, 8)
    #pragma unroll
    for (int i = 0; i < 32; i += 8)
        t[ty + i][tx] = W[(size_t)(k0 + ty + i) * ND + n0 + tx];
    __syncthreads();
    #pragma unroll
    for (int i = 0; i < 32; i += 8)
        wt[(size_t)(n0 + ty + i) * ND + k0 + tx] = __float2half(t[tx][ty + i]);
}

// ---------------------------------------------------------------------------
// Kernel C: QKV projection HMMA fp16 (A split hi+lo, W single), fp32 accum.
// CTA tile 128x64, BK=32, 24 chunks, 3-stage cp.async pipeline.
// 8 warps 4x2. Grid (65, 12, 3). Q scaled by 0.125. fp16 output.
// ---------------------------------------------------------------------------
constexpr int QLD   = 40;                     // smem stride, halfs (80 B)
constexpr int QA_SZ = 128 * QLD * 2;          // 10240 B per A matrix
constexpr int QB_SZ = 64 * QLD * 2;           // 5120 B
constexpr int QSTG  = 2 * QA_SZ + QB_SZ;      // stage: 25600 B
constexpr int QS_AHI = 0;
constexpr int QS_ALO = QA_SZ;
constexpr int QS_B   = 2 * QA_SZ;
constexpr int QSM_TOT = 3 * QSTG;             // 76800 B
constexpr int NCH = ND / 32;                  // 24

__global__ __launch_bounds__(256, 2) void qkv_hmma_kernel(
    const float* __restrict__ bq, const float* __restrict__ bk,
    const float* __restrict__ bv)
{
    extern __shared__ char smem[];
    const uint32_t smem_base = smem_to_u32(smem);
    const int tid = threadIdx.x, wid = tid >> 5, lane = tid & 31;
    const int z  = blockIdx.z;
    const int m0 = blockIdx.x * 128;
    const int h  = blockIdx.y;
    const int n0 = h * 64;
    const float* bias = (z == 0) ? bq : ((z == 1) ? bk : bv);
    __half* outb      = (z == 0) ? g_qh : ((z == 1) ? g_kh : g_vh);
    const float oscale = (z == 0) ? 0.125f : 1.0f;
    const __half* Wt = g_wt + (size_t)z * ND * ND;

    const int wm = wid >> 1;
    const int wn = wid & 1;
    const int mi = lane >> 3, lr = lane & 7;
    const int ld_row = (mi & 1) * 8 + lr;
    const int ld_col = (mi >> 1) * 8;

    // stage loader: chunk ch -> stage ch%3
    auto load_stage = [&](int ch) {
        const uint32_t sb = smem_base + (ch % 3) * QSTG;
        const int k0 = ch * 32;
        // A hi+lo: 128 rows x 32 cols = 512 16B-chunks each, 2 iters
        #pragma unroll
        for (int it = 0; it < 2; it++) {
            int lin = it * 256 + tid;
            int row = lin >> 2, c8 = (lin & 3) * 8;
            int m = m0 + row;
            int sz = (m < NM) ? 16 : 0;
            int mc = (m < NM) ? m : (NM - 1);
            uint32_t so = (uint32_t)((row * QLD + c8) * 2);
            cp_async16(sb + QS_AHI + so, g_ahi + (size_t)mc * ND + k0 + c8, sz);
            cp_async16(sb + QS_ALO + so, g_alo + (size_t)mc * ND + k0 + c8, sz);
        }
        // W tile: 64 rows x 32 cols = 256 chunks, 1 iter
        {
            int row = tid >> 2, c8 = (tid & 3) * 8;
            uint32_t so = (uint32_t)((row * QLD + c8) * 2);
            cp_async16(sb + QS_B + so, Wt + (size_t)(n0 + row) * ND + k0 + c8, 16);
        }
        CP_COMMIT();
    };

    load_stage(0);
    load_stage(1);

    float acc[2][4][4] = {};

    for (int ch = 0; ch < NCH; ch++) {
        const uint32_t sb = smem_base + (ch % 3) * QSTG;
        if (ch + 2 < NCH) { load_stage(ch + 2); CP_WAIT(2); }
        else if (ch + 1 < NCH) { CP_WAIT(1); }
        else { CP_WAIT(0); }
        __syncthreads();

        #pragma unroll
        for (int k16 = 0; k16 < 2; k16++) {
            const int kc = k16 * 16 + ld_col;
            uint32_t ah[2][4], al[2][4];
            #pragma unroll
            for (int mf = 0; mf < 2; mf++) {
                uint32_t off =
                    (uint32_t)(((wm * 32 + mf * 16 + ld_row) * QLD + kc) * 2);
                ldsm_x4(ah[mf][0], ah[mf][1], ah[mf][2], ah[mf][3],
                        sb + QS_AHI + off);
                ldsm_x4(al[mf][0], al[mf][1], al[mf][2], al[mf][3],
                        sb + QS_ALO + off);
            }
            uint32_t bf[4][2];
            #pragma unroll
            for (int nf2 = 0; nf2 < 2; nf2++) {
                uint32_t off =
                    (uint32_t)(((wn * 32 + nf2 * 16 + ld_row) * QLD + kc) * 2);
                uint32_t t0, t1, t2, t3;
                ldsm_x4(t0, t1, t2, t3, sb + QS_B + off);
                bf[nf2 * 2 + 0][0] = t0; bf[nf2 * 2 + 0][1] = t2;
                bf[nf2 * 2 + 1][0] = t1; bf[nf2 * 2 + 1][1] = t3;
            }
            #pragma unroll
            for (int mf = 0; mf < 2; mf++)
                #pragma unroll
                for (int nf = 0; nf < 4; nf++) {
                    float* c = acc[mf][nf];
                    mma_16816_f16(c[0], c[1], c[2], c[3],
                                  ah[mf][0], ah[mf][1], ah[mf][2], ah[mf][3],
                                  bf[nf][0], bf[nf][1]);
                    mma_16816_f16(c[0], c[1], c[2], c[3],
                                  al[mf][0], al[mf][1], al[mf][2], al[mf][3],
                                  bf[nf][0], bf[nf][1]);
                }
        }
        __syncthreads();
    }

    const int er = lane >> 2, ec = (lane & 3) * 2;
    #pragma unroll
    for (int mf = 0; mf < 2; mf++) {
        #pragma unroll
        for (int half_ = 0; half_ < 2; half_++) {
            const int m = m0 + wm * 32 + mf * 16 + er + half_ * 8;
            if (m >= NM) continue;
            const int bb = m / NS, ss = m - bb * NS;
            __half* op = outb + (((size_t)bb * NH + h) * NS + ss) * NHD;
            #pragma unroll
            for (int nf = 0; nf < 4; nf++) {
                const int c = wn * 32 + nf * 8 + ec;
                float ox = (acc[mf][nf][half_ * 2 + 0] + bias[n0 + c + 0]) * oscale;
                float oy = (acc[mf][nf][half_ * 2 + 1] + bias[n0 + c + 1]) * oscale;
                *(uint32_t*)(op + c) = pack_h2(ox, oy);
            }
        }
    }
}

// ---------------------------------------------------------------------------
// Kernel D: flash attention on HMMA fp16. BQ=128 per CTA, 8 warps x 16 rows,
// BK=64, 2-stage cp.async K/V pipeline. Grid (9, 12, 8).
// ---------------------------------------------------------------------------
constexpr int ALD = 72;                        // fp16 row stride
constexpr int STG = 64 * ALD * 2;              // one K or V stage: 9216 B
constexpr int SMA_Q = 0;                       // 128 x ALD = 18432 B
constexpr int SMA_K = SMA_Q + 128 * ALD * 2;   // 2 stages
constexpr int SMA_V = SMA_K + 2 * STG;         // 2 stages
constexpr int SMA_TOT = SMA_V + 2 * STG;       // 55296 B

__global__ __launch_bounds__(256, 2) void attn_hmma_kernel(
    const float* __restrict__ bias, float* __restrict__ out)
{
    extern __shared__ char smem[];
    const uint32_t smem_base = smem_to_u32(smem);
    const int tid = threadIdx.x, wid = tid >> 5, lane = tid & 31;
    const int q0 = blockIdx.x * 128;
    const int h  = blockIdx.y;
    const int b  = blockIdx.z;

    const __half* Qg = g_qh + ((size_t)(b * NH + h)) * NS * NHD;
    const __half* Kg = g_kh + ((size_t)(b * NH + h)) * NS * NHD;
    const __half* Vg = g_vh + ((size_t)(b * NH + h)) * NS * NHD;
    const float*  Bg = bias + (size_t)h * NS * NS;

    const int mi = lane >> 3, lr = lane & 7;
    const int ld_row = (mi & 1) * 8 + lr;
    const int ld_col = (mi >> 1) * 8;
    const int er = lane >> 2, ec = (lane & 3) * 2;

    const int nkt = (NS + 63) / 64;   // 17

    auto load_kv = [&](int kt) {
        const int st = kt & 1;
        #pragma unroll
        for (int it = 0; it < 2; it++) {
            int lin = it * 256 + tid;
            int row = lin >> 3, c8 = (lin & 7) * 8;
            int gr = kt * 64 + row;
            int sz = (gr < NS) ? 16 : 0;
            int grc = (gr < NS) ? gr : (NS - 1);
            uint32_t so = (uint32_t)((row * ALD + c8) * 2);
            cp_async16(smem_base + SMA_K + st * STG + so,
                       Kg + (size_t)grc * NHD + c8, sz);
            cp_async16(smem_base + SMA_V + st * STG + so,
                       Vg + (size_t)grc * NHD + c8, sz);
        }
        CP_COMMIT();
    };

    load_kv(0);

    #pragma unroll
    for (int it = 0; it < 4; it++) {
        int lin = it * 256 + tid;
        int row = lin >> 3, c8 = (lin & 7) * 8;
        int sz = (q0 + row < NS) ? 16 : 0;
        int qc = (q0 + row < NS) ? (q0 + row) : (NS - 1);
        cp_async16(smem_base + SMA_Q + (uint32_t)((row * ALD + c8) * 2),
                   Qg + (size_t)qc * NHD + c8, sz);
    }
    CP_COMMIT();
    CP_WAIT(0);
    __syncthreads();

    uint32_t qf[4][4];
    #pragma unroll
    for (int kk = 0; kk < 4; kk++) {
        uint32_t off =
            (uint32_t)(((wid * 16 + ld_row) * ALD + kk * 16 + ld_col) * 2);
        ldsm_x4(qf[kk][0], qf[kk][1], qf[kk][2], qf[kk][3],
                smem_base + SMA_Q + off);
    }

    float ctx[8][4] = {};
    float m_r[2] = {-1e30f, -1e30f};
    float l_r[2] = {0.f, 0.f};
    const int qrow0 = q0 + wid * 16 + er;
    const int qrow1 = qrow0 + 8;
    const float* br0 = Bg + (size_t)((qrow0 < NS) ? qrow0 : (NS - 1)) * NS;
    const float* br1 = Bg + (size_t)((qrow1 < NS) ? qrow1 : (NS - 1)) * NS;

    for (int kt = 0; kt < nkt; kt++) {
        const int k0 = kt * 64;
        const int st = kt & 1;
        __syncthreads();
        if (kt + 1 < nkt) {
            load_kv(kt + 1);
            CP_WAIT(1);
        } else {
            CP_WAIT(0);
        }
        __syncthreads();

        // ---- S = Q K^T ----
        float sf[8][4];
        #pragma unroll
        for (int nf = 0; nf < 8; nf++)
            #pragma unroll
            for (int c = 0; c < 4; c++) sf[nf][c] = 0.f;
        #pragma unroll
        for (int kk = 0; kk < 4; kk++) {
            uint32_t bfr[8][2];
            #pragma unroll
            for (int nf2 = 0; nf2 < 4; nf2++) {
                uint32_t off = (uint32_t)(
                    ((nf2 * 16 + ld_row) * ALD + kk * 16 + ld_col) * 2);
                uint32_t t0, t1, t2, t3;
                ldsm_x4(t0, t1, t2, t3, smem_base + SMA_K + st * STG + off);
                bfr[nf2 * 2 + 0][0] = t0; bfr[nf2 * 2 + 0][1] = t2;
                bfr[nf2 * 2 + 1][0] = t1; bfr[nf2 * 2 + 1][1] = t3;
            }
            #pragma unroll
            for (int nf = 0; nf < 8; nf++)
                mma_16816_f16(sf[nf][0], sf[nf][1], sf[nf][2], sf[nf][3],
                              qf[kk][0], qf[kk][1], qf[kk][2], qf[kk][3],
                              bfr[nf][0], bfr[nf][1]);
        }

        // ---- bias + mask + online softmax (registers) ----
        #pragma unroll
        for (int r = 0; r < 2; r++) {
            const float* br = r ? br1 : br0;
            float mx = m_r[r];
            #pragma unroll
            for (int nf = 0; nf < 8; nf++) {
                #pragma unroll
                for (int c = 0; c < 2; c++) {
                    const int kcol = k0 + nf * 8 + ec + c;
                    float s = (kcol < NS)
                        ? (sf[nf][r * 2 + c] + __ldg(br + kcol))
                        : -1e30f;
                    sf[nf][r * 2 + c] = s;
                    mx = fmaxf(mx, s);
                }
            }
            mx = fmaxf(mx, __shfl_xor_sync(0xffffffffu, mx, 1));
            mx = fmaxf(mx, __shfl_xor_sync(0xffffffffu, mx, 2));
            const float scale_f = __expf(m_r[r] - mx);
            float l = l_r[r] * scale_f;
            #pragma unroll
            for (int nf = 0; nf < 8; nf++) {
                #pragma unroll
                for (int c = 0; c < 2; c++) {
                    float p = __expf(sf[nf][r * 2 + c] - mx);
                    sf[nf][r * 2 + c] = p;
                    l += p;
                }
            }
            m_r[r] = mx;
            l_r[r] = l;
            #pragma unroll
            for (int df = 0; df < 8; df++) {
                ctx[df][r * 2 + 0] *= scale_f;
                ctx[df][r * 2 + 1] *= scale_f;
            }
        }

        // ---- pack P into A frags (register-direct) ----
        uint32_t pa[4][4];
        #pragma unroll
        for (int kk = 0; kk < 4; kk++) {
            pa[kk][0] = pack_h2(sf[2 * kk + 0][0], sf[2 * kk + 0][1]);
            pa[kk][1] = pack_h2(sf[2 * kk + 0][2], sf[2 * kk + 0][3]);
            pa[kk][2] = pack_h2(sf[2 * kk + 1][0], sf[2 * kk + 1][1]);
            pa[kk][3] = pack_h2(sf[2 * kk + 1][2], sf[2 * kk + 1][3]);
        }

        // ---- ctx += P V ----
        const int g = lane >> 3;
        #pragma unroll
        for (int kk = 0; kk < 4; kk++) {
            uint32_t vb[8][2];
            #pragma unroll
            for (int df2 = 0; df2 < 4; df2++) {
                uint32_t off = (uint32_t)(
                    ((kk * 16 + (g & 1) * 8 + (lane & 7)) * ALD
                     + df2 * 16 + (g >> 1) * 8) * 2);
                uint32_t t0, t1, t2, t3;
                ldsm_x4_trans(t0, t1, t2, t3,
                              smem_base + SMA_V + st * STG + off);
                vb[df2 * 2 + 0][0] = t0; vb[df2 * 2 + 0][1] = t1;
                vb[df2 * 2 + 1][0] = t2; vb[df2 * 2 + 1][1] = t3;
            }
            #pragma unroll
            for (int df = 0; df < 8; df++)
                mma_16816_f16(ctx[df][0], ctx[df][1], ctx[df][2], ctx[df][3],
                              pa[kk][0], pa[kk][1], pa[kk][2], pa[kk][3],
                              vb[df][0], vb[df][1]);
        }
    }

    // ---- epilogue ----
    #pragma unroll
    for (int r = 0; r < 2; r++) {
        float l = l_r[r];
        l += __shfl_xor_sync(0xffffffffu, l, 1);
        l += __shfl_xor_sync(0xffffffffu, l, 2);
        l_r[r] = l;
    }
    #pragma unroll
    for (int r = 0; r < 2; r++) {
        const int q = r ? qrow1 : qrow0;
        if (q >= NS) continue;
        const float inv = 1.0f / l_r[r];
        float* op = out + ((size_t)b * NS + q) * ND + h * NHD;
        #pragma unroll
        for (int df = 0; df < 8; df++) {
            float2 o;
            o.x = ctx[df][r * 2 + 0] * inv;
            o.y = ctx[df][r * 2 + 1] * inv;
            *(float2*)(op + df * 8 + ec) = o;
        }
    }
}

// ---------------------------------------------------------------------------
extern "C" void kernel_launch(void* const* d_in, const int* in_sizes, int n_in,
                              void* d_out, int out_size)
{
    const float* hs = (const float*)d_in[0];
    const float* rb = (const float*)d_in[1];
    const float* Wq = (const float*)d_in[2];
    const float* bq = (const float*)d_in[3];
    const float* Wk = (const float*)d_in[4];
    const float* bk = (const float*)d_in[5];
    const float* Wv = (const float*)d_in[6];
    const float* bv = (const float*)d_in[7];
    float* out = (float*)d_out;

    aconv_kernel<<<(int)(((size_t)NM * ND / 4 + 255) / 256), 256>>>(hs);
    dim3 gw(ND / 32, ND / 32, 3);
    wtrans_kernel<<<gw, dim3(32, 8)>>>(Wq, Wk, Wv);

    cudaFuncSetAttribute(qkv_hmma_kernel,
                         cudaFuncAttributeMaxDynamicSharedMemorySize, QSM_TOT);
    dim3 g1((NM + 127) / 128, NH, 3);
    qkv_hmma_kernel<<<g1, 256, QSM_TOT>>>(bq, bk, bv);

    cudaFuncSetAttribute(attn_hmma_kernel,
                         cudaFuncAttributeMaxDynamicSharedMemorySize, SMA_TOT);
    dim3 g2((NS + 127) / 128, NH, NB);
    attn_hmma_kernel<<<g2, 256, SMA_TOT>>>(rb, out);
}